// round 2
// baseline (speedup 1.0000x reference)
#include <cuda_runtime.h>
#include <cstdint>

// ---------------- problem constants ----------------
#define BSZ   2
#define NQ    5120          // 64*80
#define EDIM  576
#define HEADS 18
#define NPTS  12
#define DDEP  5             // 2*NF-1
#define HGT   64
#define WIDW  80
#define NTOK  (NQ*DDEP)     // 25600 tokens per batch in value volume

#define NOFF  (HEADS*NPTS*3)   // 648
#define NATT  (HEADS*NPTS)     // 216

// ---------------- scratch (device globals; no allocation allowed) -----------
__device__ __align__(16) float g_qsum [BSZ*NQ*EDIM];       // q + query_pos
__device__ __align__(16) float g_vproj[BSZ*NTOK*EDIM];     // value @ W_v + b_v  (118 MB)
__device__ __align__(16) float g_offs [BSZ*NQ*NOFF];       // offset logits
__device__ __align__(16) float g_attl [BSZ*NQ*NATT];       // attention logits
__device__ __align__(16) float g_samp [BSZ*NQ*EDIM];       // sampled per-head output

// ---------------- elementwise add ----------------
__global__ void add_kernel(const float* __restrict__ a, const float* __restrict__ b,
                           float* __restrict__ c, int n) {
    int i = blockIdx.x * blockDim.x + threadIdx.x;
    if (i < n) c[i] = a[i] + b[i];
}

// ---------------- fp32 SGEMM: C[M,N] = A[M,K] @ B[K,N] + bias[N] ------------
// 64x64 block tile, 16 K-tile, 256 threads, 4x4 per thread.
// Requires M%64==0, K%16==0, N%4==0 (true for all call sites here).
#define BM 64
#define BN 64
#define BKT 16

__global__ __launch_bounds__(256)
void sgemm_bias(const float* __restrict__ A, const float* __restrict__ B,
                const float* __restrict__ bias, float* __restrict__ C,
                int M, int N, int K) {
    __shared__ __align__(16) float As[BKT][BM];
    __shared__ __align__(16) float Bs[BKT][BN];

    const int tid = threadIdx.x;
    const int tx  = tid & 15;        // n-dir (4 cols each)
    const int ty  = tid >> 4;        // m-dir (4 rows each)
    const int bm  = blockIdx.y * BM;
    const int bn  = blockIdx.x * BN;

    // A tile load map: 64 rows x 4 threads/row, float4 along K
    const int arow  = tid >> 2;          // 0..63
    const int acol4 = (tid & 3) * 4;     // 0,4,8,12
    // B tile load map: 16 K-rows x 16 threads/row, float4 along N
    const int brow  = tid >> 4;          // 0..15
    const int bcol4 = (tid & 15) * 4;

    float acc[4][4] = {};

    for (int k0 = 0; k0 < K; k0 += BKT) {
        float4 av = *reinterpret_cast<const float4*>(
            &A[(size_t)(bm + arow) * K + k0 + acol4]);
        As[acol4 + 0][arow] = av.x;
        As[acol4 + 1][arow] = av.y;
        As[acol4 + 2][arow] = av.z;
        As[acol4 + 3][arow] = av.w;

        float4 bv = make_float4(0.f, 0.f, 0.f, 0.f);
        if (bn + bcol4 < N) {  // N%4==0 so base in range => whole float4 in range
            bv = *reinterpret_cast<const float4*>(
                &B[(size_t)(k0 + brow) * N + bn + bcol4]);
        }
        *reinterpret_cast<float4*>(&Bs[brow][bcol4]) = bv;

        __syncthreads();

        #pragma unroll
        for (int kk = 0; kk < BKT; kk++) {
            float4 ra = reinterpret_cast<const float4*>(As[kk])[ty];
            float4 rb = reinterpret_cast<const float4*>(Bs[kk])[tx];
            float a0 = ra.x, a1 = ra.y, a2 = ra.z, a3 = ra.w;
            float b0 = rb.x, b1 = rb.y, b2 = rb.z, b3 = rb.w;
            acc[0][0] += a0*b0; acc[0][1] += a0*b1; acc[0][2] += a0*b2; acc[0][3] += a0*b3;
            acc[1][0] += a1*b0; acc[1][1] += a1*b1; acc[1][2] += a1*b2; acc[1][3] += a1*b3;
            acc[2][0] += a2*b0; acc[2][1] += a2*b1; acc[2][2] += a2*b2; acc[2][3] += a2*b3;
            acc[3][0] += a3*b0; acc[3][1] += a3*b1; acc[3][2] += a3*b2; acc[3][3] += a3*b3;
        }
        __syncthreads();
    }

    #pragma unroll
    for (int i = 0; i < 4; i++) {
        int row = bm + ty * 4 + i;
        #pragma unroll
        for (int j = 0; j < 4; j++) {
            int col = bn + tx * 4 + j;
            if (col < N)
                C[(size_t)row * N + col] = acc[i][j] + bias[col];
        }
    }
}

// ---------------- softmax + trilinear deformable sampling -------------------
// One warp per (b, q, head); lane = head-dim channel (HD = 32).
__global__ __launch_bounds__(128)
void sample_kernel() {
    const int g = blockIdx.x * 4 + (threadIdx.x >> 5);   // warp id
    const int lane = threadIdx.x & 31;
    // g in [0, BSZ*NQ*HEADS)
    const int head = g % HEADS;
    const int bq   = g / HEADS;          // b*NQ + q
    const int q    = bq % NQ;

    // b index folded into bq for addressing vproj:
    const int b = bq / NQ;

    // ---- softmax over NPTS logits (same for all lanes; broadcast loads) ----
    const float* al = g_attl + (size_t)bq * NATT + head * NPTS;
    float logits[NPTS];
    float mx = -1e30f;
    #pragma unroll
    for (int p = 0; p < NPTS; p++) { logits[p] = al[p]; mx = fmaxf(mx, logits[p]); }
    float ssum = 0.f;
    #pragma unroll
    for (int p = 0; p < NPTS; p++) { logits[p] = __expf(logits[p] - mx); ssum += logits[p]; }
    const float inv = 1.f / ssum;

    // ---- reference point for this query ----
    const int qx = q % WIDW;
    const int qy = q / WIDW;
    const float rpx = (qx + 0.5f);            // = ((qx+0.5)/W)*W
    const float rpy = (qy + 0.5f);

    const float* off = g_offs + (size_t)bq * NOFF + head * (NPTS * 3);
    const float* vb  = g_vproj + (size_t)b * NTOK * EDIM + head * 32 + lane;

    float out = 0.f;

    #pragma unroll 4
    for (int p = 0; p < NPTS; p++) {
        const float ap = logits[p] * inv;
        // pixel coords (grid_sample, align_corners=False): u*size - 0.5
        const float px = rpx + off[p*3 + 0] - 0.5f;                 // (rx + ox/W)*W - 0.5
        const float py = rpy + off[p*3 + 1] - 0.5f;
        const float pz = off[p*3 + 2] * (float(DDEP) / 3.0f) - 0.5f; // (oz/NF)*D - 0.5

        const float x0f = floorf(px), y0f = floorf(py), z0f = floorf(pz);
        const float fx = px - x0f, fy = py - y0f, fz = pz - z0f;
        const int ix0 = (int)x0f, iy0 = (int)y0f, iz0 = (int)z0f;

        #pragma unroll
        for (int dz = 0; dz < 2; dz++) {
            const int zi = iz0 + dz;
            if (zi < 0 || zi >= DDEP) continue;
            const float wz = dz ? fz : 1.f - fz;
            #pragma unroll
            for (int dy = 0; dy < 2; dy++) {
                const int yi = iy0 + dy;
                if (yi < 0 || yi >= HGT) continue;
                const float wy = dy ? fy : 1.f - fy;
                #pragma unroll
                for (int dx = 0; dx < 2; dx++) {
                    const int xi = ix0 + dx;
                    if (xi < 0 || xi >= WIDW) continue;
                    const float wx = dx ? fx : 1.f - fx;
                    const int t = (zi * HGT + yi) * WIDW + xi;
                    out += ap * (wz * wy * wx) * vb[(size_t)t * EDIM];
                }
            }
        }
    }

    g_samp[(size_t)bq * EDIM + head * 32 + lane] = out;
}

// ---------------- launch -----------------------------------------------------
extern "C" void kernel_launch(void* const* d_in, const int* in_sizes, int n_in,
                              void* d_out, int out_size) {
    const float* query     = (const float*)d_in[0];
    const float* value     = (const float*)d_in[1];
    const float* query_pos = (const float*)d_in[2];
    const float* W_off     = (const float*)d_in[3];
    const float* b_off     = (const float*)d_in[4];
    const float* W_attn    = (const float*)d_in[5];
    const float* b_attn    = (const float*)d_in[6];
    const float* W_v       = (const float*)d_in[7];
    const float* b_v       = (const float*)d_in[8];
    const float* W_out     = (const float*)d_in[9];
    const float* b_out     = (const float*)d_in[10];
    float* out = (float*)d_out;

    float *qsum, *vproj, *offs, *attl, *samp;
    cudaGetSymbolAddress((void**)&qsum,  g_qsum);
    cudaGetSymbolAddress((void**)&vproj, g_vproj);
    cudaGetSymbolAddress((void**)&offs,  g_offs);
    cudaGetSymbolAddress((void**)&attl,  g_attl);
    cudaGetSymbolAddress((void**)&samp,  g_samp);

    // 1) q = query + query_pos
    {
        int n = BSZ * NQ * EDIM;
        add_kernel<<<n / 256, 256>>>(query, query_pos, qsum, n);
    }
    // 2) vproj = value @ W_v + b_v       (M=51200, N=576, K=576)
    {
        dim3 grid(EDIM / BN, (BSZ * NTOK) / BM);
        sgemm_bias<<<grid, 256>>>(value, W_v, b_v, vproj, BSZ * NTOK, EDIM, EDIM);
    }
    // 3) offs = qsum @ W_off + b_off     (M=10240, N=648, K=576)
    {
        dim3 grid((NOFF + BN - 1) / BN, (BSZ * NQ) / BM);
        sgemm_bias<<<grid, 256>>>(qsum, W_off, b_off, offs, BSZ * NQ, NOFF, EDIM);
    }
    // 4) attn logits = qsum @ W_attn + b_attn   (M=10240, N=216, K=576)
    {
        dim3 grid((NATT + BN - 1) / BN, (BSZ * NQ) / BM);
        sgemm_bias<<<grid, 256>>>(qsum, W_attn, b_attn, attl, BSZ * NQ, NATT, EDIM);
    }
    // 5) softmax + trilinear sampling -> samp   (one warp per (b,q,head))
    {
        int warps = BSZ * NQ * HEADS;          // 184320
        sample_kernel<<<warps / 4, 128>>>();
    }
    // 6) out = samp @ W_out + b_out      (M=10240, N=576, K=576)
    {
        dim3 grid(EDIM / BN, (BSZ * NQ) / BM);
        sgemm_bias<<<grid, 256>>>(samp, W_out, b_out, out, BSZ * NQ, EDIM, EDIM);
    }
}

// round 6
// speedup vs baseline: 1.7177x; 1.7177x over previous
#include <cuda_runtime.h>
#include <cstdint>

// ---------------- problem constants ----------------
#define BSZ   2
#define NQ    5120          // 64*80
#define EDIM  576
#define HEADS 18
#define NPTS  12
#define DDEP  5             // 2*NF-1
#define HGT   64
#define WIDW  80
#define NTOK  (NQ*DDEP)     // 25600 tokens per batch in value volume

#define NOFF  (HEADS*NPTS*3)   // 648
#define NATT  (HEADS*NPTS)     // 216

// ---------------- scratch (device globals; no allocation allowed) -----------
__device__ __align__(16) float g_qsum [BSZ*NQ*EDIM];
__device__ __align__(16) float g_vproj[BSZ*NTOK*EDIM];
__device__ __align__(16) float g_offs [BSZ*NQ*NOFF];
__device__ __align__(16) float g_attl [BSZ*NQ*NATT];
__device__ __align__(16) float g_samp [BSZ*NQ*EDIM];

// ---------------- elementwise add ----------------
__global__ void add_kernel(const float* __restrict__ a, const float* __restrict__ b,
                           float* __restrict__ c, int n) {
    int i = blockIdx.x * blockDim.x + threadIdx.x;
    if (i < n) c[i] = a[i] + b[i];
}

// ---------------- fp32 SGEMM: C[M,N] = A[M,K] @ B[K,N] + bias[N] ------------
// 128x128 CTA tile, BK=8, 8x8 per thread, 256 threads, smem double-buffer.
// Requires M%128==0, K%8==0, N%4==0 (true for all call sites here).
#define BM 128
#define BN 128
#define BK 8

__global__ __launch_bounds__(256, 2)
void sgemm_bias(const float* __restrict__ A, const float* __restrict__ B,
                const float* __restrict__ bias, float* __restrict__ C,
                int M, int N, int K) {
    __shared__ __align__(16) float As[2][BK][BM];
    __shared__ __align__(16) float Bs[2][BK][BN];

    const int tid = threadIdx.x;
    const int bm  = blockIdx.y * BM;
    const int bn  = blockIdx.x * BN;

    // A tile load: 128 rows x 8 K; 2 threads/row, one float4 each
    const int arow = tid >> 1;           // 0..127
    const int acol = (tid & 1) * 4;      // 0 or 4
    // B tile load: 8 K-rows x 128 cols; 32 threads/row, one float4 each
    const int brow = tid >> 5;           // 0..7
    const int bcol = (tid & 31) * 4;     // 0..124

    // compute mapping: 16x16 threads, each 8x8 (two 4x4 quads split by +64)
    const int tx = tid & 15;             // n-dir
    const int ty = tid >> 4;             // m-dir

    const float* Ag = A + (size_t)(bm + arow) * K + acol;
    const float* Bg = B + (size_t)brow * N + bn + bcol;
    const bool bvalid = (bn + bcol) < N;   // N%4==0 -> whole float4 in-range

    // ---- preload tile 0 ----
    float4 aR = *reinterpret_cast<const float4*>(Ag);
    float4 bR = bvalid ? *reinterpret_cast<const float4*>(Bg)
                       : make_float4(0.f, 0.f, 0.f, 0.f);
    As[0][acol + 0][arow] = aR.x;
    As[0][acol + 1][arow] = aR.y;
    As[0][acol + 2][arow] = aR.z;
    As[0][acol + 3][arow] = aR.w;
    *reinterpret_cast<float4*>(&Bs[0][brow][bcol]) = bR;
    __syncthreads();

    float acc[8][8] = {};
    float af[8], bf[8];

    const int nt = K / BK;
    int c = 0;
    for (int t = 0; t < nt; t++) {
        if (t + 1 < nt) {
            aR = *reinterpret_cast<const float4*>(Ag + (size_t)(t + 1) * BK);
            bR = bvalid ? *reinterpret_cast<const float4*>(Bg + (size_t)(t + 1) * BK * N)
                        : make_float4(0.f, 0.f, 0.f, 0.f);
        }

        #pragma unroll
        for (int kk = 0; kk < BK; kk++) {
            *reinterpret_cast<float4*>(&af[0]) =
                *reinterpret_cast<const float4*>(&As[c][kk][ty * 4]);
            *reinterpret_cast<float4*>(&af[4]) =
                *reinterpret_cast<const float4*>(&As[c][kk][ty * 4 + 64]);
            *reinterpret_cast<float4*>(&bf[0]) =
                *reinterpret_cast<const float4*>(&Bs[c][kk][tx * 4]);
            *reinterpret_cast<float4*>(&bf[4]) =
                *reinterpret_cast<const float4*>(&Bs[c][kk][tx * 4 + 64]);
            #pragma unroll
            for (int i = 0; i < 8; i++)
                #pragma unroll
                for (int j = 0; j < 8; j++)
                    acc[i][j] += af[i] * bf[j];
        }

        if (t + 1 < nt) {
            // safe: other buffer's readers finished before last iteration's sync
            As[c ^ 1][acol + 0][arow] = aR.x;
            As[c ^ 1][acol + 1][arow] = aR.y;
            As[c ^ 1][acol + 2][arow] = aR.z;
            As[c ^ 1][acol + 3][arow] = aR.w;
            *reinterpret_cast<float4*>(&Bs[c ^ 1][brow][bcol]) = bR;
        }
        __syncthreads();
        c ^= 1;
    }

    // ---- epilogue ----
    #pragma unroll
    for (int i = 0; i < 8; i++) {
        const int row = bm + ty * 4 + (i < 4 ? i : 64 + (i - 4));
        #pragma unroll
        for (int j = 0; j < 8; j++) {
            const int col = bn + tx * 4 + (j < 4 ? j : 64 + (j - 4));
            if (col < N)
                C[(size_t)row * N + col] = acc[i][j] + bias[col];
        }
    }
}

// ---------------- softmax + trilinear deformable sampling -------------------
// One warp per (b, q, head); lane = head-dim channel (HD = 32).
__global__ __launch_bounds__(128)
void sample_kernel() {
    const int g = blockIdx.x * 4 + (threadIdx.x >> 5);
    const int lane = threadIdx.x & 31;
    const int head = g % HEADS;
    const int bq   = g / HEADS;
    const int q    = bq % NQ;
    const int b    = bq / NQ;

    // ---- softmax over NPTS logits ----
    const float* al = g_attl + (size_t)bq * NATT + head * NPTS;
    float logits[NPTS];
    float mx = -1e30f;
    #pragma unroll
    for (int p = 0; p < NPTS; p++) { logits[p] = al[p]; mx = fmaxf(mx, logits[p]); }
    float ssum = 0.f;
    #pragma unroll
    for (int p = 0; p < NPTS; p++) { logits[p] = __expf(logits[p] - mx); ssum += logits[p]; }
    const float inv = 1.f / ssum;

    const int qx = q % WIDW;
    const int qy = q / WIDW;
    const float rpx = (qx + 0.5f);
    const float rpy = (qy + 0.5f);

    const float* off = g_offs + (size_t)bq * NOFF + head * (NPTS * 3);
    const float* vb  = g_vproj + (size_t)b * NTOK * EDIM + head * 32 + lane;

    float out = 0.f;

    #pragma unroll 4
    for (int p = 0; p < NPTS; p++) {
        const float ap = logits[p] * inv;
        const float px = rpx + off[p*3 + 0] - 0.5f;
        const float py = rpy + off[p*3 + 1] - 0.5f;
        const float pz = off[p*3 + 2] * (float(DDEP) / 3.0f) - 0.5f;

        const float x0f = floorf(px), y0f = floorf(py), z0f = floorf(pz);
        const float fx = px - x0f, fy = py - y0f, fz = pz - z0f;
        const int ix0 = (int)x0f, iy0 = (int)y0f, iz0 = (int)z0f;

        #pragma unroll
        for (int dz = 0; dz < 2; dz++) {
            const int zi = iz0 + dz;
            if (zi < 0 || zi >= DDEP) continue;
            const float wz = dz ? fz : 1.f - fz;
            #pragma unroll
            for (int dy = 0; dy < 2; dy++) {
                const int yi = iy0 + dy;
                if (yi < 0 || yi >= HGT) continue;
                const float wy = dy ? fy : 1.f - fy;
                #pragma unroll
                for (int dx = 0; dx < 2; dx++) {
                    const int xi = ix0 + dx;
                    if (xi < 0 || xi >= WIDW) continue;
                    const float wx = dx ? fx : 1.f - fx;
                    const int t = (zi * HGT + yi) * WIDW + xi;
                    out += ap * (wz * wy * wx) * vb[(size_t)t * EDIM];
                }
            }
        }
    }

    g_samp[(size_t)bq * EDIM + head * 32 + lane] = out;
}

// ---------------- launch -----------------------------------------------------
extern "C" void kernel_launch(void* const* d_in, const int* in_sizes, int n_in,
                              void* d_out, int out_size) {
    const float* query     = (const float*)d_in[0];
    const float* value     = (const float*)d_in[1];
    const float* query_pos = (const float*)d_in[2];
    const float* W_off     = (const float*)d_in[3];
    const float* b_off     = (const float*)d_in[4];
    const float* W_attn    = (const float*)d_in[5];
    const float* b_attn    = (const float*)d_in[6];
    const float* W_v       = (const float*)d_in[7];
    const float* b_v       = (const float*)d_in[8];
    const float* W_out     = (const float*)d_in[9];
    const float* b_out     = (const float*)d_in[10];
    float* out = (float*)d_out;

    float *qsum, *vproj, *offs, *attl, *samp;
    cudaGetSymbolAddress((void**)&qsum,  g_qsum);
    cudaGetSymbolAddress((void**)&vproj, g_vproj);
    cudaGetSymbolAddress((void**)&offs,  g_offs);
    cudaGetSymbolAddress((void**)&attl,  g_attl);
    cudaGetSymbolAddress((void**)&samp,  g_samp);

    // 1) q = query + query_pos
    {
        int n = BSZ * NQ * EDIM;
        add_kernel<<<n / 256, 256>>>(query, query_pos, qsum, n);
    }
    // 2) vproj = value @ W_v + b_v       (M=51200, N=576, K=576)
    {
        dim3 grid((EDIM + BN - 1) / BN, (BSZ * NTOK) / BM);
        sgemm_bias<<<grid, 256>>>(value, W_v, b_v, vproj, BSZ * NTOK, EDIM, EDIM);
    }
    // 3) offs = qsum @ W_off + b_off     (M=10240, N=648, K=576)
    {
        dim3 grid((NOFF + BN - 1) / BN, (BSZ * NQ) / BM);
        sgemm_bias<<<grid, 256>>>(qsum, W_off, b_off, offs, BSZ * NQ, NOFF, EDIM);
    }
    // 4) attn logits = qsum @ W_attn + b_attn   (M=10240, N=216, K=576)
    {
        dim3 grid((NATT + BN - 1) / BN, (BSZ * NQ) / BM);
        sgemm_bias<<<grid, 256>>>(qsum, W_attn, b_attn, attl, BSZ * NQ, NATT, EDIM);
    }
    // 5) softmax + trilinear sampling -> samp
    {
        int warps = BSZ * NQ * HEADS;          // 184320
        sample_kernel<<<warps / 4, 128>>>();
    }
    // 6) out = samp @ W_out + b_out      (M=10240, N=576, K=576)
    {
        dim3 grid((EDIM + BN - 1) / BN, (BSZ * NQ) / BM);
        sgemm_bias<<<grid, 256>>>(samp, W_out, b_out, out, BSZ * NQ, EDIM, EDIM);
    }
}

// round 8
// speedup vs baseline: 2.8701x; 1.6709x over previous
#include <cuda_runtime.h>
#include <cuda_bf16.h>
#include <cstdint>

// ---------------- problem constants ----------------
#define BSZ   2
#define NQ    5120
#define EDIM  576
#define HEADS 18
#define NPTS  12
#define DDEP  5
#define HGT   64
#define WIDW  80
#define NTOK  (NQ*DDEP)        // 25600
#define NOFF  (HEADS*NPTS*3)   // 648
#define NATT  (HEADS*NPTS)     // 216
#define KDIM  576
#define NCH   18               // K chunks of 32
#define NIT   54               // 3 split-products * 18 chunks

// ---------------- scratch (device globals) -----------------------------------
__device__ __align__(16) __nv_bfloat16 g_qhi [BSZ*NQ*EDIM];
__device__ __align__(16) __nv_bfloat16 g_qlo [BSZ*NQ*EDIM];
__device__ __align__(16) __nv_bfloat16 g_vhi [BSZ*NTOK*EDIM];
__device__ __align__(16) __nv_bfloat16 g_vlo [BSZ*NTOK*EDIM];
__device__ __align__(16) float         g_vproj[BSZ*NTOK*EDIM];
__device__ __align__(16) float         g_offs [BSZ*NQ*NOFF];
__device__ __align__(16) float         g_attl [BSZ*NQ*NATT];
__device__ __align__(16) __nv_bfloat16 g_shi [BSZ*NQ*EDIM];
__device__ __align__(16) __nv_bfloat16 g_slo [BSZ*NQ*EDIM];
// transposed + split weights: [N][K] K-major
__device__ __align__(16) __nv_bfloat16 g_wv_hi [EDIM*EDIM];
__device__ __align__(16) __nv_bfloat16 g_wv_lo [EDIM*EDIM];
__device__ __align__(16) __nv_bfloat16 g_wo_hi [NOFF*EDIM];
__device__ __align__(16) __nv_bfloat16 g_wo_lo [NOFF*EDIM];
__device__ __align__(16) __nv_bfloat16 g_wa_hi [NATT*EDIM];
__device__ __align__(16) __nv_bfloat16 g_wa_lo [NATT*EDIM];
__device__ __align__(16) __nv_bfloat16 g_wu_hi [EDIM*EDIM];
__device__ __align__(16) __nv_bfloat16 g_wu_lo [EDIM*EDIM];

// ---------------- helpers -----------------------------------------------------
__device__ __forceinline__ uint32_t smem_u32(const void* p) {
    uint32_t a;
    asm("{ .reg .u64 t; cvta.to.shared.u64 t, %1; cvt.u32.u64 %0, t; }" : "=r"(a) : "l"(p));
    return a;
}
__device__ __forceinline__ void mma16816(float* c, const uint32_t* a, uint32_t b0, uint32_t b1) {
    asm volatile("mma.sync.aligned.m16n8k16.row.col.f32.bf16.bf16.f32 "
        "{%0,%1,%2,%3}, {%4,%5,%6,%7}, {%8,%9}, {%0,%1,%2,%3};"
        : "+f"(c[0]), "+f"(c[1]), "+f"(c[2]), "+f"(c[3])
        : "r"(a[0]), "r"(a[1]), "r"(a[2]), "r"(a[3]), "r"(b0), "r"(b1));
}
#define LDSM_X4(d, addr) \
    asm volatile("ldmatrix.sync.aligned.m8n8.x4.shared.b16 {%0,%1,%2,%3}, [%4];" \
        : "=r"((d)[0]), "=r"((d)[1]), "=r"((d)[2]), "=r"((d)[3]) : "r"(addr))

// ---------------- conversion kernels -----------------------------------------
__global__ void addsplit_kernel(const float* __restrict__ a, const float* __restrict__ b,
                                __nv_bfloat16* __restrict__ hi, __nv_bfloat16* __restrict__ lo, int n) {
    int i = blockIdx.x * blockDim.x + threadIdx.x;
    if (i < n) {
        float x = a[i] + b[i];
        __nv_bfloat16 h = __float2bfloat16(x);
        hi[i] = h;
        lo[i] = __float2bfloat16(x - __bfloat162float(h));
    }
}
__global__ void split_kernel(const float* __restrict__ a,
                             __nv_bfloat16* __restrict__ hi, __nv_bfloat16* __restrict__ lo, int n) {
    int i = blockIdx.x * blockDim.x + threadIdx.x;
    if (i < n) {
        float x = a[i];
        __nv_bfloat16 h = __float2bfloat16(x);
        hi[i] = h;
        lo[i] = __float2bfloat16(x - __bfloat162float(h));
    }
}
// W[K][N] -> Wt[N][K], split
__global__ void tsplit_kernel(const float* __restrict__ W,
                              __nv_bfloat16* __restrict__ hi, __nv_bfloat16* __restrict__ lo,
                              int K, int N) {
    int i = blockIdx.x * blockDim.x + threadIdx.x;
    if (i < K * N) {
        int n = i / K, k = i - n * K;
        float x = W[(size_t)k * N + n];
        __nv_bfloat16 h = __float2bfloat16(x);
        hi[i] = h;
        lo[i] = __float2bfloat16(x - __bfloat162float(h));
    }
}

// ---------------- split-bf16 tensor-core GEMM (mma.sync) ---------------------
// C[M,N] = A[M,K] @ Bt[N,K]^T + bias.  A/Bt given as bf16 (hi,lo).
// CTA 128x128, BK=32, 8 warps (warp tile 32x64), cp.async double-buffer.
// 3 split products folded into one 54-chunk K loop.
// Requires M%128==0, N%8==0.
#define ROWB 80   // padded smem row stride bytes (64B data + 16B pad)

__global__ __launch_bounds__(256, 2)
void mma_gemm(const __nv_bfloat16* __restrict__ Ahi, const __nv_bfloat16* __restrict__ Alo,
              const __nv_bfloat16* __restrict__ Bhi, const __nv_bfloat16* __restrict__ Blo,
              const float* __restrict__ bias, float* __restrict__ C, int N) {
    __shared__ __align__(16) char smA[2][128 * ROWB];
    __shared__ __align__(16) char smB[2][128 * ROWB];

    const int tid  = threadIdx.x;
    const int lane = tid & 31;
    const int wid  = tid >> 5;
    const int wm   = (wid >> 1) * 32;     // warp m-offset (0,32,64,96)
    const int wn   = (wid & 1) * 64;      // warp n-offset (0,64)
    const int bm   = blockIdx.y * 128;
    const int bn   = blockIdx.x * 128;

    const uint32_t baseA0 = smem_u32(smA[0]);
    const uint32_t baseA1 = smem_u32(smA[1]);
    const uint32_t baseB0 = smem_u32(smB[0]);
    const uint32_t baseB1 = smem_u32(smB[1]);

    // loader coords: 512 16B-chunks per tile, 2 per thread
    const int lr = tid >> 2;      // rows lr and lr+64
    const int lc = tid & 3;       // 16B chunk col (k sub-block)

    auto issue = [&](int it, int buf) {
        const int phase = (it >= 2 * NCH) ? 2 : (it >= NCH ? 1 : 0);
        const int k0 = (it - phase * NCH) * 32;
        const __nv_bfloat16* As = (phase == 2) ? Alo : Ahi;
        const __nv_bfloat16* Bs = (phase == 1) ? Blo : Bhi;
        const uint32_t bA = buf ? baseA1 : baseA0;
        const uint32_t bB = buf ? baseB1 : baseB0;
        #pragma unroll
        for (int i = 0; i < 2; i++) {
            const int r = lr + i * 64;
            const uint32_t dA = bA + r * ROWB + lc * 16;
            const void* gA = As + (size_t)(bm + r) * KDIM + k0 + lc * 8;
            asm volatile("cp.async.cg.shared.global [%0], [%1], 16;"
                         :: "r"(dA), "l"(gA) : "memory");
            const int brow = bn + r;
            const int vsz = (brow < N) ? 16 : 0;
            const uint32_t dB = bB + r * ROWB + lc * 16;
            const void* gB = Bs + (size_t)(brow < N ? brow : 0) * KDIM + k0 + lc * 8;
            asm volatile("cp.async.cg.shared.global [%0], [%1], 16, %2;"
                         :: "r"(dB), "l"(gB), "r"(vsz) : "memory");
        }
        asm volatile("cp.async.commit_group;" ::: "memory");
    };

    float acc[2][8][4] = {};

    issue(0, 0);

    for (int it = 0; it < NIT; it++) {
        const int buf = it & 1;
        if (it + 1 < NIT) {
            issue(it + 1, buf ^ 1);
            asm volatile("cp.async.wait_group 1;" ::: "memory");
        } else {
            asm volatile("cp.async.wait_group 0;" ::: "memory");
        }
        __syncthreads();

        const uint32_t bA = buf ? baseA1 : baseA0;
        const uint32_t bB = buf ? baseB1 : baseB0;

        #pragma unroll
        for (int ks = 0; ks < 2; ks++) {
            uint32_t a[2][4];
            #pragma unroll
            for (int mt = 0; mt < 2; mt++) {
                const uint32_t addr = bA
                    + (uint32_t)(wm + mt * 16 + (lane & 15)) * ROWB
                    + (uint32_t)(ks * 2 + (lane >> 4)) * 16;
                LDSM_X4(a[mt], addr);
            }
            #pragma unroll
            for (int np = 0; np < 4; np++) {   // pair of 8-wide n tiles
                uint32_t b[4];
                const uint32_t addr = bB
                    + (uint32_t)(wn + np * 16 + ((lane & 16) >> 1) + (lane & 7)) * ROWB
                    + (uint32_t)(ks * 2 + ((lane >> 3) & 1)) * 16;
                LDSM_X4(b, addr);
                #pragma unroll
                for (int mt = 0; mt < 2; mt++) {
                    mma16816(acc[mt][np * 2],     a[mt], b[0], b[1]);
                    mma16816(acc[mt][np * 2 + 1], a[mt], b[2], b[3]);
                }
            }
        }
        __syncthreads();
    }

    // ---- epilogue ----
    const int group = lane >> 2, tig = lane & 3;
    #pragma unroll
    for (int mt = 0; mt < 2; mt++) {
        #pragma unroll
        for (int nt = 0; nt < 8; nt++) {
            const int colbase = bn + wn + nt * 8;
            if (colbase >= N) continue;          // N%8==0 -> whole 8-tile valid or not
            const int col = colbase + tig * 2;
            const int m0  = bm + wm + mt * 16 + group;
            const float b0v = bias[col], b1v = bias[col + 1];
            C[(size_t)m0 * N + col]           = acc[mt][nt][0] + b0v;
            C[(size_t)m0 * N + col + 1]       = acc[mt][nt][1] + b1v;
            C[(size_t)(m0 + 8) * N + col]     = acc[mt][nt][2] + b0v;
            C[(size_t)(m0 + 8) * N + col + 1] = acc[mt][nt][3] + b1v;
        }
    }
}

// ---------------- softmax + trilinear deformable sampling --------------------
__global__ __launch_bounds__(128)
void sample_kernel() {
    const int g = blockIdx.x * 4 + (threadIdx.x >> 5);
    const int lane = threadIdx.x & 31;
    const int head = g % HEADS;
    const int bq   = g / HEADS;
    const int q    = bq % NQ;
    const int b    = bq / NQ;

    const float* al = g_attl + (size_t)bq * NATT + head * NPTS;
    float logits[NPTS];
    float mx = -1e30f;
    #pragma unroll
    for (int p = 0; p < NPTS; p++) { logits[p] = al[p]; mx = fmaxf(mx, logits[p]); }
    float ssum = 0.f;
    #pragma unroll
    for (int p = 0; p < NPTS; p++) { logits[p] = __expf(logits[p] - mx); ssum += logits[p]; }
    const float inv = 1.f / ssum;

    const int qx = q % WIDW;
    const int qy = q / WIDW;
    const float rpx = qx + 0.5f;
    const float rpy = qy + 0.5f;

    const float* off = g_offs + (size_t)bq * NOFF + head * (NPTS * 3);
    const float* vb  = g_vproj + (size_t)b * NTOK * EDIM + head * 32 + lane;

    float out = 0.f;

    #pragma unroll 4
    for (int p = 0; p < NPTS; p++) {
        const float ap = logits[p] * inv;
        const float px = rpx + off[p*3 + 0] - 0.5f;
        const float py = rpy + off[p*3 + 1] - 0.5f;
        const float pz = off[p*3 + 2] * (float(DDEP) / 3.0f) - 0.5f;

        const float x0f = floorf(px), y0f = floorf(py), z0f = floorf(pz);
        const float fx = px - x0f, fy = py - y0f, fz = pz - z0f;
        const int ix0 = (int)x0f, iy0 = (int)y0f, iz0 = (int)z0f;

        #pragma unroll
        for (int dz = 0; dz < 2; dz++) {
            const int zi = iz0 + dz;
            if (zi < 0 || zi >= DDEP) continue;
            const float wz = dz ? fz : 1.f - fz;
            #pragma unroll
            for (int dy = 0; dy < 2; dy++) {
                const int yi = iy0 + dy;
                if (yi < 0 || yi >= HGT) continue;
                const float wy = dy ? fy : 1.f - fy;
                #pragma unroll
                for (int dx = 0; dx < 2; dx++) {
                    const int xi = ix0 + dx;
                    if (xi < 0 || xi >= WIDW) continue;
                    const float wx = dx ? fx : 1.f - fx;
                    const int t = (zi * HGT + yi) * WIDW + xi;
                    out += ap * (wz * wy * wx) * vb[(size_t)t * EDIM];
                }
            }
        }
    }

    const size_t oi = (size_t)bq * EDIM + head * 32 + lane;
    __nv_bfloat16 h = __float2bfloat16(out);
    g_shi[oi] = h;
    g_slo[oi] = __float2bfloat16(out - __bfloat162float(h));
}

// ---------------- launch ------------------------------------------------------
extern "C" void kernel_launch(void* const* d_in, const int* in_sizes, int n_in,
                              void* d_out, int out_size) {
    const float* query     = (const float*)d_in[0];
    const float* value     = (const float*)d_in[1];
    const float* query_pos = (const float*)d_in[2];
    const float* W_off     = (const float*)d_in[3];
    const float* b_off     = (const float*)d_in[4];
    const float* W_attn    = (const float*)d_in[5];
    const float* b_attn    = (const float*)d_in[6];
    const float* W_v       = (const float*)d_in[7];
    const float* b_v       = (const float*)d_in[8];
    const float* W_out     = (const float*)d_in[9];
    const float* b_out     = (const float*)d_in[10];
    float* out = (float*)d_out;

    __nv_bfloat16 *qhi, *qlo, *vhi, *vlo, *shi, *slo;
    __nv_bfloat16 *wvh, *wvl, *woh, *wol, *wah, *wal, *wuh, *wul;
    float *vproj, *offs, *attl;
    cudaGetSymbolAddress((void**)&qhi, g_qhi);   cudaGetSymbolAddress((void**)&qlo, g_qlo);
    cudaGetSymbolAddress((void**)&vhi, g_vhi);   cudaGetSymbolAddress((void**)&vlo, g_vlo);
    cudaGetSymbolAddress((void**)&shi, g_shi);   cudaGetSymbolAddress((void**)&slo, g_slo);
    cudaGetSymbolAddress((void**)&wvh, g_wv_hi); cudaGetSymbolAddress((void**)&wvl, g_wv_lo);
    cudaGetSymbolAddress((void**)&woh, g_wo_hi); cudaGetSymbolAddress((void**)&wol, g_wo_lo);
    cudaGetSymbolAddress((void**)&wah, g_wa_hi); cudaGetSymbolAddress((void**)&wal, g_wa_lo);
    cudaGetSymbolAddress((void**)&wuh, g_wu_hi); cudaGetSymbolAddress((void**)&wul, g_wu_lo);
    cudaGetSymbolAddress((void**)&vproj, g_vproj);
    cudaGetSymbolAddress((void**)&offs,  g_offs);
    cudaGetSymbolAddress((void**)&attl,  g_attl);

    // 1) conversions
    { int n = BSZ*NQ*EDIM;   addsplit_kernel<<<(n+255)/256, 256>>>(query, query_pos, qhi, qlo, n); }
    { int n = BSZ*NTOK*EDIM; split_kernel<<<(n+255)/256, 256>>>(value, vhi, vlo, n); }
    { int n = EDIM*EDIM; tsplit_kernel<<<(n+255)/256, 256>>>(W_v,   wvh, wvl, EDIM, EDIM); }
    { int n = EDIM*NOFF; tsplit_kernel<<<(n+255)/256, 256>>>(W_off, woh, wol, EDIM, NOFF); }
    { int n = EDIM*NATT; tsplit_kernel<<<(n+255)/256, 256>>>(W_attn, wah, wal, EDIM, NATT); }
    { int n = EDIM*EDIM; tsplit_kernel<<<(n+255)/256, 256>>>(W_out, wuh, wul, EDIM, EDIM); }

    // 2) vproj = value @ W_v + b_v       (M=51200, N=576)
    {
        dim3 grid((EDIM + 127) / 128, (BSZ * NTOK) / 128);
        mma_gemm<<<grid, 256>>>(vhi, vlo, wvh, wvl, b_v, vproj, EDIM);
    }
    // 3) offs = q @ W_off + b_off        (M=10240, N=648)
    {
        dim3 grid((NOFF + 127) / 128, (BSZ * NQ) / 128);
        mma_gemm<<<grid, 256>>>(qhi, qlo, woh, wol, b_off, offs, NOFF);
    }
    // 4) attl = q @ W_attn + b_attn      (M=10240, N=216)
    {
        dim3 grid((NATT + 127) / 128, (BSZ * NQ) / 128);
        mma_gemm<<<grid, 256>>>(qhi, qlo, wah, wal, b_attn, attl, NATT);
    }
    // 5) softmax + trilinear sampling
    {
        int warps = BSZ * NQ * HEADS;
        sample_kernel<<<warps / 4, 128>>>();
    }
    // 6) out = samp @ W_out + b_out      (M=10240, N=576)
    {
        dim3 grid((EDIM + 127) / 128, (BSZ * NQ) / 128);
        mma_gemm<<<grid, 256>>>(shi, slo, wuh, wul, b_out, out, EDIM);
    }
}

// round 9
// speedup vs baseline: 4.4166x; 1.5388x over previous
#include <cuda_runtime.h>
#include <cuda_bf16.h>
#include <cuda_fp16.h>
#include <cstdint>

// ---------------- problem constants ----------------
#define BSZ   2
#define NQ    5120
#define EDIM  576
#define HEADS 18
#define NPTS  12
#define DDEP  5
#define HGT   64
#define WIDW  80
#define NTOK  (NQ*DDEP)        // 25600
#define NOFF  (HEADS*NPTS*3)   // 648
#define NATT  (HEADS*NPTS)     // 216
#define KDIM  576
#define NCH   18               // K chunks of 32

// ---------------- scratch (device globals) -----------------------------------
__device__ __align__(16) __nv_bfloat16 g_qhi [BSZ*NQ*EDIM];
__device__ __align__(16) __nv_bfloat16 g_qlo [BSZ*NQ*EDIM];
__device__ __align__(16) __half        g_qh  [BSZ*NQ*EDIM];
__device__ __align__(16) __half        g_vh  [BSZ*NTOK*EDIM];
__device__ __align__(16) __half        g_vprojH[BSZ*NTOK*EDIM];
__device__ __align__(16) float         g_offs [BSZ*NQ*NOFF];
__device__ __align__(16) float         g_attl [BSZ*NQ*NATT];
__device__ __align__(16) __half        g_sampH[BSZ*NQ*EDIM];
// transposed weights: [N][K] K-major
__device__ __align__(16) __half        g_wv  [EDIM*EDIM];
__device__ __align__(16) __nv_bfloat16 g_wo_hi [NOFF*EDIM];
__device__ __align__(16) __nv_bfloat16 g_wo_lo [NOFF*EDIM];
__device__ __align__(16) __half        g_wa  [NATT*EDIM];
__device__ __align__(16) __half        g_wu  [EDIM*EDIM];

// ---------------- helpers -----------------------------------------------------
__device__ __forceinline__ uint32_t smem_u32(const void* p) {
    uint32_t a;
    asm("{ .reg .u64 t; cvta.to.shared.u64 t, %1; cvt.u32.u64 %0, t; }" : "=r"(a) : "l"(p));
    return a;
}
template<typename T>
__device__ __forceinline__ void mma16816(float* c, const uint32_t* a, uint32_t b0, uint32_t b1);
template<>
__device__ __forceinline__ void mma16816<__nv_bfloat16>(float* c, const uint32_t* a, uint32_t b0, uint32_t b1) {
    asm volatile("mma.sync.aligned.m16n8k16.row.col.f32.bf16.bf16.f32 "
        "{%0,%1,%2,%3}, {%4,%5,%6,%7}, {%8,%9}, {%0,%1,%2,%3};"
        : "+f"(c[0]), "+f"(c[1]), "+f"(c[2]), "+f"(c[3])
        : "r"(a[0]), "r"(a[1]), "r"(a[2]), "r"(a[3]), "r"(b0), "r"(b1));
}
template<>
__device__ __forceinline__ void mma16816<__half>(float* c, const uint32_t* a, uint32_t b0, uint32_t b1) {
    asm volatile("mma.sync.aligned.m16n8k16.row.col.f32.f16.f16.f32 "
        "{%0,%1,%2,%3}, {%4,%5,%6,%7}, {%8,%9}, {%0,%1,%2,%3};"
        : "+f"(c[0]), "+f"(c[1]), "+f"(c[2]), "+f"(c[3])
        : "r"(a[0]), "r"(a[1]), "r"(a[2]), "r"(a[3]), "r"(b0), "r"(b1));
}
#define LDSM_X4(d, addr) \
    asm volatile("ldmatrix.sync.aligned.m8n8.x4.shared.b16 {%0,%1,%2,%3}, [%4];" \
        : "=r"((d)[0]), "=r"((d)[1]), "=r"((d)[2]), "=r"((d)[3]) : "r"(addr))

__device__ __forceinline__ void store_out(float* C, size_t idx, float v) { C[idx] = v; }
__device__ __forceinline__ void store_out(__half* C, size_t idx, float v) { C[idx] = __float2half(v); }

// ---------------- conversion kernels -----------------------------------------
// q + qpos -> bf16 hi/lo + fp16
__global__ void addsplit3_kernel(const float* __restrict__ a, const float* __restrict__ b,
                                 __nv_bfloat16* __restrict__ hi, __nv_bfloat16* __restrict__ lo,
                                 __half* __restrict__ h16, int n) {
    int i = blockIdx.x * blockDim.x + threadIdx.x;
    if (i < n) {
        float x = a[i] + b[i];
        __nv_bfloat16 h = __float2bfloat16(x);
        hi[i] = h;
        lo[i] = __float2bfloat16(x - __bfloat162float(h));
        h16[i] = __float2half(x);
    }
}
// fp32 -> fp16 (vectorized x4; n % 4 == 0)
__global__ void half4_kernel(const float4* __restrict__ a, uint2* __restrict__ h, int n4) {
    int i = blockIdx.x * blockDim.x + threadIdx.x;
    if (i < n4) {
        float4 v = a[i];
        __half2 h0 = __floats2half2_rn(v.x, v.y);
        __half2 h1 = __floats2half2_rn(v.z, v.w);
        uint2 r;
        r.x = *reinterpret_cast<uint32_t*>(&h0);
        r.y = *reinterpret_cast<uint32_t*>(&h1);
        h[i] = r;
    }
}
// W[K][N] -> Wt[N][K], bf16 split
__global__ void tsplit_kernel(const float* __restrict__ W,
                              __nv_bfloat16* __restrict__ hi, __nv_bfloat16* __restrict__ lo,
                              int K, int N) {
    int i = blockIdx.x * blockDim.x + threadIdx.x;
    if (i < K * N) {
        int n = i / K, k = i - n * K;
        float x = W[(size_t)k * N + n];
        __nv_bfloat16 h = __float2bfloat16(x);
        hi[i] = h;
        lo[i] = __float2bfloat16(x - __bfloat162float(h));
    }
}
// W[K][N] -> Wt[N][K], fp16
__global__ void thalf_kernel(const float* __restrict__ W, __half* __restrict__ h,
                             int K, int N) {
    int i = blockIdx.x * blockDim.x + threadIdx.x;
    if (i < K * N) {
        int n = i / K, k = i - n * K;
        h[i] = __float2half(W[(size_t)k * N + n]);
    }
}

// ---------------- tensor-core GEMM (mma.sync) --------------------------------
// C[M,N] = A[M,K] @ Bt[N,K]^T + bias.
// SPLIT3: 3-product bf16 split (Ahi*Bhi + Ahi*Blo + Alo*Bhi); else single product.
// CTA 128x128, BK=32, 8 warps (warp tile 32x64), cp.async double-buffer.
// Requires M%128==0, N%8==0.
#define ROWB 80   // padded smem row stride bytes (64B data + 16B pad)

template<bool SPLIT3, typename InT, typename OutT>
__global__ __launch_bounds__(256, 2)
void mma_gemm(const InT* __restrict__ Ahi, const InT* __restrict__ Alo,
              const InT* __restrict__ Bhi, const InT* __restrict__ Blo,
              const float* __restrict__ bias, OutT* __restrict__ C, int N) {
    __shared__ __align__(16) char smA[2][128 * ROWB];
    __shared__ __align__(16) char smB[2][128 * ROWB];

    constexpr int NIT = SPLIT3 ? 3 * NCH : NCH;

    const int tid  = threadIdx.x;
    const int lane = tid & 31;
    const int wid  = tid >> 5;
    const int wm   = (wid >> 1) * 32;
    const int wn   = (wid & 1) * 64;
    const int bm   = blockIdx.y * 128;
    const int bn   = blockIdx.x * 128;

    const uint32_t baseA0 = smem_u32(smA[0]);
    const uint32_t baseA1 = smem_u32(smA[1]);
    const uint32_t baseB0 = smem_u32(smB[0]);
    const uint32_t baseB1 = smem_u32(smB[1]);

    const int lr = tid >> 2;      // rows lr and lr+64
    const int lc = tid & 3;       // 16B chunk col

    auto issue = [&](int it, int buf) {
        int phase = 0, k0;
        if (SPLIT3) {
            phase = (it >= 2 * NCH) ? 2 : (it >= NCH ? 1 : 0);
            k0 = (it - phase * NCH) * 32;
        } else {
            k0 = it * 32;
        }
        const InT* As = (SPLIT3 && phase == 2) ? Alo : Ahi;
        const InT* Bs = (SPLIT3 && phase == 1) ? Blo : Bhi;
        const uint32_t bA = buf ? baseA1 : baseA0;
        const uint32_t bB = buf ? baseB1 : baseB0;
        #pragma unroll
        for (int i = 0; i < 2; i++) {
            const int r = lr + i * 64;
            const uint32_t dA = bA + r * ROWB + lc * 16;
            const void* gA = As + (size_t)(bm + r) * KDIM + k0 + lc * 8;
            asm volatile("cp.async.cg.shared.global [%0], [%1], 16;"
                         :: "r"(dA), "l"(gA) : "memory");
            const int brow = bn + r;
            const int vsz = (brow < N) ? 16 : 0;
            const uint32_t dB = bB + r * ROWB + lc * 16;
            const void* gB = Bs + (size_t)(brow < N ? brow : 0) * KDIM + k0 + lc * 8;
            asm volatile("cp.async.cg.shared.global [%0], [%1], 16, %2;"
                         :: "r"(dB), "l"(gB), "r"(vsz) : "memory");
        }
        asm volatile("cp.async.commit_group;" ::: "memory");
    };

    float acc[2][8][4] = {};

    issue(0, 0);

    for (int it = 0; it < NIT; it++) {
        const int buf = it & 1;
        if (it + 1 < NIT) {
            issue(it + 1, buf ^ 1);
            asm volatile("cp.async.wait_group 1;" ::: "memory");
        } else {
            asm volatile("cp.async.wait_group 0;" ::: "memory");
        }
        __syncthreads();

        const uint32_t bA = buf ? baseA1 : baseA0;
        const uint32_t bB = buf ? baseB1 : baseB0;

        #pragma unroll
        for (int ks = 0; ks < 2; ks++) {
            uint32_t a[2][4];
            #pragma unroll
            for (int mt = 0; mt < 2; mt++) {
                const uint32_t addr = bA
                    + (uint32_t)(wm + mt * 16 + (lane & 15)) * ROWB
                    + (uint32_t)(ks * 2 + (lane >> 4)) * 16;
                LDSM_X4(a[mt], addr);
            }
            #pragma unroll
            for (int np = 0; np < 4; np++) {
                uint32_t b[4];
                const uint32_t addr = bB
                    + (uint32_t)(wn + np * 16 + ((lane & 16) >> 1) + (lane & 7)) * ROWB
                    + (uint32_t)(ks * 2 + ((lane >> 3) & 1)) * 16;
                LDSM_X4(b, addr);
                #pragma unroll
                for (int mt = 0; mt < 2; mt++) {
                    mma16816<InT>(acc[mt][np * 2],     a[mt], b[0], b[1]);
                    mma16816<InT>(acc[mt][np * 2 + 1], a[mt], b[2], b[3]);
                }
            }
        }
        __syncthreads();
    }

    // ---- epilogue ----
    const int group = lane >> 2, tig = lane & 3;
    #pragma unroll
    for (int mt = 0; mt < 2; mt++) {
        #pragma unroll
        for (int nt = 0; nt < 8; nt++) {
            const int colbase = bn + wn + nt * 8;
            if (colbase >= N) continue;
            const int col = colbase + tig * 2;
            const int m0  = bm + wm + mt * 16 + group;
            const float b0v = bias[col], b1v = bias[col + 1];
            store_out(C, (size_t)m0 * N + col,           acc[mt][nt][0] + b0v);
            store_out(C, (size_t)m0 * N + col + 1,       acc[mt][nt][1] + b1v);
            store_out(C, (size_t)(m0 + 8) * N + col,     acc[mt][nt][2] + b0v);
            store_out(C, (size_t)(m0 + 8) * N + col + 1, acc[mt][nt][3] + b1v);
        }
    }
}

// ---------------- softmax + trilinear deformable sampling --------------------
// One warp per (b, q, head); lane = head-dim channel. fp16 value buffer.
__global__ __launch_bounds__(256)
void sample_kernel() {
    const int g = blockIdx.x * 8 + (threadIdx.x >> 5);
    const int lane = threadIdx.x & 31;
    const int head = g % HEADS;
    const int bq   = g / HEADS;
    const int q    = bq % NQ;
    const int b    = bq / NQ;

    const float* al = g_attl + (size_t)bq * NATT + head * NPTS;
    float logits[NPTS];
    float mx = -1e30f;
    #pragma unroll
    for (int p = 0; p < NPTS; p++) { logits[p] = al[p]; mx = fmaxf(mx, logits[p]); }
    float ssum = 0.f;
    #pragma unroll
    for (int p = 0; p < NPTS; p++) { logits[p] = __expf(logits[p] - mx); ssum += logits[p]; }
    const float inv = 1.f / ssum;

    const int qx = q % WIDW;
    const int qy = q / WIDW;
    const float rpx = qx + 0.5f;
    const float rpy = qy + 0.5f;

    const float* off = g_offs + (size_t)bq * NOFF + head * (NPTS * 3);
    const __half* vb = g_vprojH + (size_t)b * NTOK * EDIM + head * 32 + lane;

    float out = 0.f;

    #pragma unroll 4
    for (int p = 0; p < NPTS; p++) {
        const float ap = logits[p] * inv;
        const float px = rpx + off[p*3 + 0] - 0.5f;
        const float py = rpy + off[p*3 + 1] - 0.5f;
        const float pz = off[p*3 + 2] * (float(DDEP) / 3.0f) - 0.5f;

        const float x0f = floorf(px), y0f = floorf(py), z0f = floorf(pz);
        const float fx = px - x0f, fy = py - y0f, fz = pz - z0f;
        const int ix0 = (int)x0f, iy0 = (int)y0f, iz0 = (int)z0f;

        #pragma unroll
        for (int dz = 0; dz < 2; dz++) {
            const int zi = iz0 + dz;
            if (zi < 0 || zi >= DDEP) continue;
            const float wz = dz ? fz : 1.f - fz;
            #pragma unroll
            for (int dy = 0; dy < 2; dy++) {
                const int yi = iy0 + dy;
                if (yi < 0 || yi >= HGT) continue;
                const float wy = dy ? fy : 1.f - fy;
                #pragma unroll
                for (int dx = 0; dx < 2; dx++) {
                    const int xi = ix0 + dx;
                    if (xi < 0 || xi >= WIDW) continue;
                    const float wx = dx ? fx : 1.f - fx;
                    const int t = (zi * HGT + yi) * WIDW + xi;
                    out += ap * (wz * wy * wx) * __half2float(vb[(size_t)t * EDIM]);
                }
            }
        }
    }

    g_sampH[(size_t)bq * EDIM + head * 32 + lane] = __float2half(out);
}

// ---------------- launch ------------------------------------------------------
extern "C" void kernel_launch(void* const* d_in, const int* in_sizes, int n_in,
                              void* d_out, int out_size) {
    const float* query     = (const float*)d_in[0];
    const float* value     = (const float*)d_in[1];
    const float* query_pos = (const float*)d_in[2];
    const float* W_off     = (const float*)d_in[3];
    const float* b_off     = (const float*)d_in[4];
    const float* W_attn    = (const float*)d_in[5];
    const float* b_attn    = (const float*)d_in[6];
    const float* W_v       = (const float*)d_in[7];
    const float* b_v       = (const float*)d_in[8];
    const float* W_out     = (const float*)d_in[9];
    const float* b_out     = (const float*)d_in[10];
    float* out = (float*)d_out;

    __nv_bfloat16 *qhi, *qlo, *woh, *wol;
    __half *qh, *vh, *vprojH, *sampH, *wv, *wa, *wu;
    float *offs, *attl;
    cudaGetSymbolAddress((void**)&qhi, g_qhi);   cudaGetSymbolAddress((void**)&qlo, g_qlo);
    cudaGetSymbolAddress((void**)&qh,  g_qh);
    cudaGetSymbolAddress((void**)&vh,  g_vh);    cudaGetSymbolAddress((void**)&vprojH, g_vprojH);
    cudaGetSymbolAddress((void**)&sampH, g_sampH);
    cudaGetSymbolAddress((void**)&wv,  g_wv);
    cudaGetSymbolAddress((void**)&woh, g_wo_hi); cudaGetSymbolAddress((void**)&wol, g_wo_lo);
    cudaGetSymbolAddress((void**)&wa,  g_wa);    cudaGetSymbolAddress((void**)&wu,  g_wu);
    cudaGetSymbolAddress((void**)&offs, g_offs);
    cudaGetSymbolAddress((void**)&attl, g_attl);

    // 1) conversions
    { int n = BSZ*NQ*EDIM;
      addsplit3_kernel<<<(n+255)/256, 256>>>(query, query_pos, qhi, qlo, qh, n); }
    { int n4 = (BSZ*NTOK*EDIM)/4;
      half4_kernel<<<(n4+255)/256, 256>>>((const float4*)value, (uint2*)vh, n4); }
    { int n = EDIM*EDIM; thalf_kernel<<<(n+255)/256, 256>>>(W_v,   wv, EDIM, EDIM); }
    { int n = EDIM*NOFF; tsplit_kernel<<<(n+255)/256, 256>>>(W_off, woh, wol, EDIM, NOFF); }
    { int n = EDIM*NATT; thalf_kernel<<<(n+255)/256, 256>>>(W_attn, wa, EDIM, NATT); }
    { int n = EDIM*EDIM; thalf_kernel<<<(n+255)/256, 256>>>(W_out, wu, EDIM, EDIM); }

    // 2) vproj = value @ W_v + b_v       (M=51200, N=576) fp16 single-product
    {
        dim3 grid((EDIM + 127) / 128, (BSZ * NTOK) / 128);
        mma_gemm<false, __half, __half><<<grid, 256>>>(vh, vh, wv, wv, b_v, vprojH, EDIM);
    }
    // 3) offs = q @ W_off + b_off        (M=10240, N=648) bf16 3-product split
    {
        dim3 grid((NOFF + 127) / 128, (BSZ * NQ) / 128);
        mma_gemm<true, __nv_bfloat16, float><<<grid, 256>>>(qhi, qlo, woh, wol, b_off, offs, NOFF);
    }
    // 4) attl = q @ W_attn + b_attn      (M=10240, N=216) fp16 single-product
    {
        dim3 grid((NATT + 127) / 128, (BSZ * NQ) / 128);
        mma_gemm<false, __half, float><<<grid, 256>>>(qh, qh, wa, wa, b_attn, attl, NATT);
    }
    // 5) softmax + trilinear sampling
    {
        int warps = BSZ * NQ * HEADS;          // 184320
        sample_kernel<<<warps / 8, 256>>>();
    }
    // 6) out = samp @ W_out + b_out      (M=10240, N=576) fp16 single-product
    {
        dim3 grid((EDIM + 127) / 128, (BSZ * NQ) / 128);
        mma_gemm<false, __half, float><<<grid, 256>>>(sampH, sampH, wu, wu, b_out, out, EDIM);
    }
}

// round 10
// speedup vs baseline: 4.4358x; 1.0043x over previous
#include <cuda_runtime.h>
#include <cuda_bf16.h>
#include <cuda_fp16.h>
#include <cstdint>

// ---------------- problem constants ----------------
#define BSZ   2
#define NQ    5120
#define EDIM  576
#define HEADS 18
#define NPTS  12
#define DDEP  5
#define HGT   64
#define WIDW  80
#define NTOK  (NQ*DDEP)        // 25600
#define NOFF  (HEADS*NPTS*3)   // 648
#define NATT  (HEADS*NPTS)     // 216
#define KDIM  576
#define NCH   18               // K chunks of 32

// ---------------- scratch (device globals) -----------------------------------
__device__ __align__(16) __nv_bfloat16 g_qhi [BSZ*NQ*EDIM];
__device__ __align__(16) __nv_bfloat16 g_qlo [BSZ*NQ*EDIM];
__device__ __align__(16) __half        g_qh  [BSZ*NQ*EDIM];
__device__ __align__(16) __half        g_vh  [BSZ*NTOK*EDIM];
__device__ __align__(16) __half        g_vprojH[BSZ*NTOK*EDIM];
__device__ __align__(16) float         g_offs [BSZ*NQ*NOFF];
__device__ __align__(16) float         g_attl [BSZ*NQ*NATT];
__device__ __align__(16) __half        g_sampH[BSZ*NQ*EDIM];
// transposed weights: [N][K] K-major
__device__ __align__(16) __half        g_wv  [EDIM*EDIM];
__device__ __align__(16) __nv_bfloat16 g_wo_hi [NOFF*EDIM];
__device__ __align__(16) __nv_bfloat16 g_wo_lo [NOFF*EDIM];
__device__ __align__(16) __half        g_wa  [NATT*EDIM];
__device__ __align__(16) __half        g_wu  [EDIM*EDIM];

// ---------------- helpers -----------------------------------------------------
__device__ __forceinline__ uint32_t smem_u32(const void* p) {
    uint32_t a;
    asm("{ .reg .u64 t; cvta.to.shared.u64 t, %1; cvt.u32.u64 %0, t; }" : "=r"(a) : "l"(p));
    return a;
}
template<typename T>
__device__ __forceinline__ void mma16816(float* c, const uint32_t* a, uint32_t b0, uint32_t b1);
template<>
__device__ __forceinline__ void mma16816<__nv_bfloat16>(float* c, const uint32_t* a, uint32_t b0, uint32_t b1) {
    asm volatile("mma.sync.aligned.m16n8k16.row.col.f32.bf16.bf16.f32 "
        "{%0,%1,%2,%3}, {%4,%5,%6,%7}, {%8,%9}, {%0,%1,%2,%3};"
        : "+f"(c[0]), "+f"(c[1]), "+f"(c[2]), "+f"(c[3])
        : "r"(a[0]), "r"(a[1]), "r"(a[2]), "r"(a[3]), "r"(b0), "r"(b1));
}
template<>
__device__ __forceinline__ void mma16816<__half>(float* c, const uint32_t* a, uint32_t b0, uint32_t b1) {
    asm volatile("mma.sync.aligned.m16n8k16.row.col.f32.f16.f16.f32 "
        "{%0,%1,%2,%3}, {%4,%5,%6,%7}, {%8,%9}, {%0,%1,%2,%3};"
        : "+f"(c[0]), "+f"(c[1]), "+f"(c[2]), "+f"(c[3])
        : "r"(a[0]), "r"(a[1]), "r"(a[2]), "r"(a[3]), "r"(b0), "r"(b1));
}
#define LDSM_X4(d, addr) \
    asm volatile("ldmatrix.sync.aligned.m8n8.x4.shared.b16 {%0,%1,%2,%3}, [%4];" \
        : "=r"((d)[0]), "=r"((d)[1]), "=r"((d)[2]), "=r"((d)[3]) : "r"(addr))

__device__ __forceinline__ void store_out(float* C, size_t idx, float v) { C[idx] = v; }
__device__ __forceinline__ void store_out(__half* C, size_t idx, float v) { C[idx] = __float2half(v); }

// ---------------- conversion kernels -----------------------------------------
__global__ void addsplit3_kernel(const float* __restrict__ a, const float* __restrict__ b,
                                 __nv_bfloat16* __restrict__ hi, __nv_bfloat16* __restrict__ lo,
                                 __half* __restrict__ h16, int n) {
    int i = blockIdx.x * blockDim.x + threadIdx.x;
    if (i < n) {
        float x = a[i] + b[i];
        __nv_bfloat16 h = __float2bfloat16(x);
        hi[i] = h;
        lo[i] = __float2bfloat16(x - __bfloat162float(h));
        h16[i] = __float2half(x);
    }
}
__global__ void half4_kernel(const float4* __restrict__ a, uint2* __restrict__ h, int n4) {
    int i = blockIdx.x * blockDim.x + threadIdx.x;
    if (i < n4) {
        float4 v = a[i];
        __half2 h0 = __floats2half2_rn(v.x, v.y);
        __half2 h1 = __floats2half2_rn(v.z, v.w);
        uint2 r;
        r.x = *reinterpret_cast<uint32_t*>(&h0);
        r.y = *reinterpret_cast<uint32_t*>(&h1);
        h[i] = r;
    }
}
__global__ void tsplit_kernel(const float* __restrict__ W,
                              __nv_bfloat16* __restrict__ hi, __nv_bfloat16* __restrict__ lo,
                              int K, int N) {
    int i = blockIdx.x * blockDim.x + threadIdx.x;
    if (i < K * N) {
        int n = i / K, k = i - n * K;
        float x = W[(size_t)k * N + n];
        __nv_bfloat16 h = __float2bfloat16(x);
        hi[i] = h;
        lo[i] = __float2bfloat16(x - __bfloat162float(h));
    }
}
__global__ void thalf_kernel(const float* __restrict__ W, __half* __restrict__ h,
                             int K, int N) {
    int i = blockIdx.x * blockDim.x + threadIdx.x;
    if (i < K * N) {
        int n = i / K, k = i - n * K;
        h[i] = __float2half(W[(size_t)k * N + n]);
    }
}

// ---------------- tensor-core GEMM (mma.sync) --------------------------------
#define ROWB 80   // padded smem row stride bytes (64B data + 16B pad)

template<bool SPLIT3, typename InT, typename OutT>
__global__ __launch_bounds__(256, 2)
void mma_gemm(const InT* __restrict__ Ahi, const InT* __restrict__ Alo,
              const InT* __restrict__ Bhi, const InT* __restrict__ Blo,
              const float* __restrict__ bias, OutT* __restrict__ C, int N) {
    __shared__ __align__(16) char smA[2][128 * ROWB];
    __shared__ __align__(16) char smB[2][128 * ROWB];

    constexpr int NIT = SPLIT3 ? 3 * NCH : NCH;

    const int tid  = threadIdx.x;
    const int lane = tid & 31;
    const int wid  = tid >> 5;
    const int wm   = (wid >> 1) * 32;
    const int wn   = (wid & 1) * 64;
    const int bm   = blockIdx.y * 128;
    const int bn   = blockIdx.x * 128;

    const uint32_t baseA0 = smem_u32(smA[0]);
    const uint32_t baseA1 = smem_u32(smA[1]);
    const uint32_t baseB0 = smem_u32(smB[0]);
    const uint32_t baseB1 = smem_u32(smB[1]);

    const int lr = tid >> 2;
    const int lc = tid & 3;

    auto issue = [&](int it, int buf) {
        int phase = 0, k0;
        if (SPLIT3) {
            phase = (it >= 2 * NCH) ? 2 : (it >= NCH ? 1 : 0);
            k0 = (it - phase * NCH) * 32;
        } else {
            k0 = it * 32;
        }
        const InT* As = (SPLIT3 && phase == 2) ? Alo : Ahi;
        const InT* Bs = (SPLIT3 && phase == 1) ? Blo : Bhi;
        const uint32_t bA = buf ? baseA1 : baseA0;
        const uint32_t bB = buf ? baseB1 : baseB0;
        #pragma unroll
        for (int i = 0; i < 2; i++) {
            const int r = lr + i * 64;
            const uint32_t dA = bA + r * ROWB + lc * 16;
            const void* gA = As + (size_t)(bm + r) * KDIM + k0 + lc * 8;
            asm volatile("cp.async.cg.shared.global [%0], [%1], 16;"
                         :: "r"(dA), "l"(gA) : "memory");
            const int brow = bn + r;
            const int vsz = (brow < N) ? 16 : 0;
            const uint32_t dB = bB + r * ROWB + lc * 16;
            const void* gB = Bs + (size_t)(brow < N ? brow : 0) * KDIM + k0 + lc * 8;
            asm volatile("cp.async.cg.shared.global [%0], [%1], 16, %2;"
                         :: "r"(dB), "l"(gB), "r"(vsz) : "memory");
        }
        asm volatile("cp.async.commit_group;" ::: "memory");
    };

    float acc[2][8][4] = {};

    issue(0, 0);

    for (int it = 0; it < NIT; it++) {
        const int buf = it & 1;
        if (it + 1 < NIT) {
            issue(it + 1, buf ^ 1);
            asm volatile("cp.async.wait_group 1;" ::: "memory");
        } else {
            asm volatile("cp.async.wait_group 0;" ::: "memory");
        }
        __syncthreads();

        const uint32_t bA = buf ? baseA1 : baseA0;
        const uint32_t bB = buf ? baseB1 : baseB0;

        #pragma unroll
        for (int ks = 0; ks < 2; ks++) {
            uint32_t a[2][4];
            #pragma unroll
            for (int mt = 0; mt < 2; mt++) {
                const uint32_t addr = bA
                    + (uint32_t)(wm + mt * 16 + (lane & 15)) * ROWB
                    + (uint32_t)(ks * 2 + (lane >> 4)) * 16;
                LDSM_X4(a[mt], addr);
            }
            #pragma unroll
            for (int np = 0; np < 4; np++) {
                uint32_t b[4];
                const uint32_t addr = bB
                    + (uint32_t)(wn + np * 16 + ((lane & 16) >> 1) + (lane & 7)) * ROWB
                    + (uint32_t)(ks * 2 + ((lane >> 3) & 1)) * 16;
                LDSM_X4(b, addr);
                #pragma unroll
                for (int mt = 0; mt < 2; mt++) {
                    mma16816<InT>(acc[mt][np * 2],     a[mt], b[0], b[1]);
                    mma16816<InT>(acc[mt][np * 2 + 1], a[mt], b[2], b[3]);
                }
            }
        }
        __syncthreads();
    }

    const int group = lane >> 2, tig = lane & 3;
    #pragma unroll
    for (int mt = 0; mt < 2; mt++) {
        #pragma unroll
        for (int nt = 0; nt < 8; nt++) {
            const int colbase = bn + wn + nt * 8;
            if (colbase >= N) continue;
            const int col = colbase + tig * 2;
            const int m0  = bm + wm + mt * 16 + group;
            const float b0v = bias[col], b1v = bias[col + 1];
            store_out(C, (size_t)m0 * N + col,           acc[mt][nt][0] + b0v);
            store_out(C, (size_t)m0 * N + col + 1,       acc[mt][nt][1] + b1v);
            store_out(C, (size_t)(m0 + 8) * N + col,     acc[mt][nt][2] + b0v);
            store_out(C, (size_t)(m0 + 8) * N + col + 1, acc[mt][nt][3] + b1v);
        }
    }
}

// ---------------- softmax + trilinear deformable sampling --------------------
// One warp handles TWO heads of one (b,q): lanes 0-15 -> head 2p, lanes 16-31
// -> head 2p+1. Each lane covers 2 channels via __half2. Branchless corners
// (clamped index, zero weight) keep the two half-warps convergent.
__global__ __launch_bounds__(256)
void sample_kernel() {
    const int g    = blockIdx.x * 8 + (threadIdx.x >> 5);   // warp id
    const int lane = threadIdx.x & 31;
    const int pair = g % (HEADS / 2);          // 0..8
    const int bq   = g / (HEADS / 2);
    const int q    = bq % NQ;
    const int b    = bq / NQ;
    const int head = pair * 2 + (lane >> 4);   // half-warp selects head
    const int sl   = lane & 15;                // channel pair index (0..15)

    // ---- softmax over NPTS logits (broadcast within half-warp) ----
    const float* al = g_attl + (size_t)bq * NATT + head * NPTS;
    float logits[NPTS];
    float mx = -1e30f;
    #pragma unroll
    for (int p = 0; p < NPTS; p++) { logits[p] = al[p]; mx = fmaxf(mx, logits[p]); }
    float ssum = 0.f;
    #pragma unroll
    for (int p = 0; p < NPTS; p++) { logits[p] = __expf(logits[p] - mx); ssum += logits[p]; }
    const float inv = 1.f / ssum;

    const int qx = q % WIDW;
    const int qy = q / WIDW;
    const float rpx = qx + 0.5f;
    const float rpy = qy + 0.5f;

    const float* off = g_offs + (size_t)bq * NOFF + head * (NPTS * 3);
    // half2 view: channels (2*sl, 2*sl+1) of this head
    const __half2* vb = reinterpret_cast<const __half2*>(
        g_vprojH + (size_t)b * NTOK * EDIM + head * 32) + sl;

    float ox = 0.f, oy = 0.f;

    #pragma unroll 4
    for (int p = 0; p < NPTS; p++) {
        const float ap = logits[p] * inv;
        const float px = rpx + off[p*3 + 0] - 0.5f;
        const float py = rpy + off[p*3 + 1] - 0.5f;
        const float pz = off[p*3 + 2] * (float(DDEP) / 3.0f) - 0.5f;

        const float x0f = floorf(px), y0f = floorf(py), z0f = floorf(pz);
        const float fx = px - x0f, fy = py - y0f, fz = pz - z0f;
        const int ix0 = (int)x0f, iy0 = (int)y0f, iz0 = (int)z0f;

        #pragma unroll
        for (int dz = 0; dz < 2; dz++) {
            const int zi = iz0 + dz;
            const float wz = dz ? fz : 1.f - fz;
            const bool zok = (zi >= 0) & (zi < DDEP);
            const int zc = min(max(zi, 0), DDEP - 1);
            #pragma unroll
            for (int dy = 0; dy < 2; dy++) {
                const int yi = iy0 + dy;
                const float wy = dy ? fy : 1.f - fy;
                const bool yok = (yi >= 0) & (yi < HGT);
                const int yc = min(max(yi, 0), HGT - 1);
                #pragma unroll
                for (int dx = 0; dx < 2; dx++) {
                    const int xi = ix0 + dx;
                    const float wx = dx ? fx : 1.f - fx;
                    const bool xok = (xi >= 0) & (xi < WIDW);
                    const int xc = min(max(xi, 0), WIDW - 1);
                    float w = ap * wz * wy * wx;
                    w = (zok & yok & xok) ? w : 0.f;
                    const int t = (zc * HGT + yc) * WIDW + xc;
                    const float2 vf = __half22float2(vb[(size_t)t * (EDIM / 2)]);
                    ox += w * vf.x;
                    oy += w * vf.y;
                }
            }
        }
    }

    reinterpret_cast<__half2*>(g_sampH + (size_t)bq * EDIM + head * 32)[sl] =
        __floats2half2_rn(ox, oy);
}

// ---------------- launch ------------------------------------------------------
extern "C" void kernel_launch(void* const* d_in, const int* in_sizes, int n_in,
                              void* d_out, int out_size) {
    const float* query     = (const float*)d_in[0];
    const float* value     = (const float*)d_in[1];
    const float* query_pos = (const float*)d_in[2];
    const float* W_off     = (const float*)d_in[3];
    const float* b_off     = (const float*)d_in[4];
    const float* W_attn    = (const float*)d_in[5];
    const float* b_attn    = (const float*)d_in[6];
    const float* W_v       = (const float*)d_in[7];
    const float* b_v       = (const float*)d_in[8];
    const float* W_out     = (const float*)d_in[9];
    const float* b_out     = (const float*)d_in[10];
    float* out = (float*)d_out;

    __nv_bfloat16 *qhi, *qlo, *woh, *wol;
    __half *qh, *vh, *vprojH, *sampH, *wv, *wa, *wu;
    float *offs, *attl;
    cudaGetSymbolAddress((void**)&qhi, g_qhi);   cudaGetSymbolAddress((void**)&qlo, g_qlo);
    cudaGetSymbolAddress((void**)&qh,  g_qh);
    cudaGetSymbolAddress((void**)&vh,  g_vh);    cudaGetSymbolAddress((void**)&vprojH, g_vprojH);
    cudaGetSymbolAddress((void**)&sampH, g_sampH);
    cudaGetSymbolAddress((void**)&wv,  g_wv);
    cudaGetSymbolAddress((void**)&woh, g_wo_hi); cudaGetSymbolAddress((void**)&wol, g_wo_lo);
    cudaGetSymbolAddress((void**)&wa,  g_wa);    cudaGetSymbolAddress((void**)&wu,  g_wu);
    cudaGetSymbolAddress((void**)&offs, g_offs);
    cudaGetSymbolAddress((void**)&attl, g_attl);

    // 1) conversions
    { int n = BSZ*NQ*EDIM;
      addsplit3_kernel<<<(n+255)/256, 256>>>(query, query_pos, qhi, qlo, qh, n); }
    { int n4 = (BSZ*NTOK*EDIM)/4;
      half4_kernel<<<(n4+255)/256, 256>>>((const float4*)value, (uint2*)vh, n4); }
    { int n = EDIM*EDIM; thalf_kernel<<<(n+255)/256, 256>>>(W_v,   wv, EDIM, EDIM); }
    { int n = EDIM*NOFF; tsplit_kernel<<<(n+255)/256, 256>>>(W_off, woh, wol, EDIM, NOFF); }
    { int n = EDIM*NATT; thalf_kernel<<<(n+255)/256, 256>>>(W_attn, wa, EDIM, NATT); }
    { int n = EDIM*EDIM; thalf_kernel<<<(n+255)/256, 256>>>(W_out, wu, EDIM, EDIM); }

    // 2) vproj = value @ W_v + b_v       (M=51200, N=576) fp16 single-product
    {
        dim3 grid((EDIM + 127) / 128, (BSZ * NTOK) / 128);
        mma_gemm<false, __half, __half><<<grid, 256>>>(vh, vh, wv, wv, b_v, vprojH, EDIM);
    }
    // 3) offs = q @ W_off + b_off        (M=10240, N=648) bf16 3-product split
    {
        dim3 grid((NOFF + 127) / 128, (BSZ * NQ) / 128);
        mma_gemm<true, __nv_bfloat16, float><<<grid, 256>>>(qhi, qlo, woh, wol, b_off, offs, NOFF);
    }
    // 4) attl = q @ W_attn + b_attn      (M=10240, N=216) fp16 single-product
    {
        dim3 grid((NATT + 127) / 128, (BSZ * NQ) / 128);
        mma_gemm<false, __half, float><<<grid, 256>>>(qh, qh, wa, wa, b_attn, attl, NATT);
    }
    // 5) softmax + trilinear sampling (2 heads per warp, half2 channels)
    {
        int warps = BSZ * NQ * (HEADS / 2);    // 92160
        sample_kernel<<<warps / 8, 256>>>();
    }
    // 6) out = samp @ W_out + b_out      (M=10240, N=576) fp16 single-product
    {
        dim3 grid((EDIM + 127) / 128, (BSZ * NQ) / 128);
        mma_gemm<false, __half, float><<<grid, 256>>>(sampH, sampH, wu, wu, b_out, out, EDIM);
    }
}

// round 12
// speedup vs baseline: 5.1867x; 1.1693x over previous
#include <cuda_runtime.h>
#include <cuda_bf16.h>
#include <cuda_fp16.h>
#include <cstdint>

// ---------------- problem constants ----------------
#define BSZ   2
#define NQ    5120
#define EDIM  576
#define HEADS 18
#define NPTS  12
#define DDEP  5
#define HGT   64
#define WIDW  80
#define NTOK  (NQ*DDEP)        // 25600
#define NOFF  (HEADS*NPTS*3)   // 648
#define NATT  (HEADS*NPTS)     // 216
#define KDIM  576
#define NCH   18               // K chunks of 32
#define NV4   ((BSZ*NTOK*EDIM)/4)   // float4 count of value

// ---------------- scratch (device globals) -----------------------------------
__device__ __align__(16) __nv_bfloat16 g_qhi [BSZ*NQ*EDIM];
__device__ __align__(16) __nv_bfloat16 g_qlo [BSZ*NQ*EDIM];
__device__ __align__(16) __half        g_qh  [BSZ*NQ*EDIM];
__device__ __align__(16) __half        g_vh  [BSZ*NTOK*EDIM];
__device__ __align__(16) __half        g_vprojH[BSZ*NTOK*EDIM];
__device__ __align__(16) float         g_offs [BSZ*NQ*NOFF];
__device__ __align__(16) float         g_attl [BSZ*NQ*NATT];
__device__ __align__(16) __half        g_sampH[BSZ*NQ*EDIM];
// transposed weights: [N][K] K-major
__device__ __align__(16) __half        g_wv  [EDIM*EDIM];
__device__ __align__(16) __nv_bfloat16 g_wo_hi [NOFF*EDIM];
__device__ __align__(16) __nv_bfloat16 g_wo_lo [NOFF*EDIM];
__device__ __align__(16) __half        g_wa  [NATT*EDIM];
__device__ __align__(16) __half        g_wu  [EDIM*EDIM];

// ---------------- helpers -----------------------------------------------------
__device__ __forceinline__ uint32_t smem_u32(const void* p) {
    uint32_t a;
    asm("{ .reg .u64 t; cvta.to.shared.u64 t, %1; cvt.u32.u64 %0, t; }" : "=r"(a) : "l"(p));
    return a;
}
template<typename T>
__device__ __forceinline__ void mma16816(float* c, const uint32_t* a, uint32_t b0, uint32_t b1);
template<>
__device__ __forceinline__ void mma16816<__nv_bfloat16>(float* c, const uint32_t* a, uint32_t b0, uint32_t b1) {
    asm volatile("mma.sync.aligned.m16n8k16.row.col.f32.bf16.bf16.f32 "
        "{%0,%1,%2,%3}, {%4,%5,%6,%7}, {%8,%9}, {%0,%1,%2,%3};"
        : "+f"(c[0]), "+f"(c[1]), "+f"(c[2]), "+f"(c[3])
        : "r"(a[0]), "r"(a[1]), "r"(a[2]), "r"(a[3]), "r"(b0), "r"(b1));
}
template<>
__device__ __forceinline__ void mma16816<__half>(float* c, const uint32_t* a, uint32_t b0, uint32_t b1) {
    asm volatile("mma.sync.aligned.m16n8k16.row.col.f32.f16.f16.f32 "
        "{%0,%1,%2,%3}, {%4,%5,%6,%7}, {%8,%9}, {%0,%1,%2,%3};"
        : "+f"(c[0]), "+f"(c[1]), "+f"(c[2]), "+f"(c[3])
        : "r"(a[0]), "r"(a[1]), "r"(a[2]), "r"(a[3]), "r"(b0), "r"(b1));
}
#define LDSM_X4(d, addr) \
    asm volatile("ldmatrix.sync.aligned.m8n8.x4.shared.b16 {%0,%1,%2,%3}, [%4];" \
        : "=r"((d)[0]), "=r"((d)[1]), "=r"((d)[2]), "=r"((d)[3]) : "r"(addr))

__device__ __forceinline__ void store_out(float* C, size_t idx, float v) { C[idx] = v; }
__device__ __forceinline__ void store_out(__half* C, size_t idx, float v) { C[idx] = __float2half(v); }

// ---------------- conversion kernels -----------------------------------------
__global__ void addsplit3_kernel(const float* __restrict__ a, const float* __restrict__ b,
                                 __nv_bfloat16* __restrict__ hi, __nv_bfloat16* __restrict__ lo,
                                 __half* __restrict__ h16, int n) {
    int i = blockIdx.x * blockDim.x + threadIdx.x;
    if (i < n) {
        float x = a[i] + b[i];
        __nv_bfloat16 h = __float2bfloat16(x);
        hi[i] = h;
        lo[i] = __float2bfloat16(x - __bfloat162float(h));
        h16[i] = __float2half(x);
    }
}

// One kernel: value -> fp16 (vectorized) + all weight transposes/conversions.
__global__ void megaconv_kernel(const float* __restrict__ value,
                                const float* __restrict__ W_v,
                                const float* __restrict__ W_off,
                                const float* __restrict__ W_attn,
                                const float* __restrict__ W_out) {
    int i = blockIdx.x * blockDim.x + threadIdx.x;
    // region 0: value fp32x4 -> fp16x4
    if (i < NV4) {
        float4 v = reinterpret_cast<const float4*>(value)[i];
        __half2 h0 = __floats2half2_rn(v.x, v.y);
        __half2 h1 = __floats2half2_rn(v.z, v.w);
        uint2 r;
        r.x = *reinterpret_cast<uint32_t*>(&h0);
        r.y = *reinterpret_cast<uint32_t*>(&h1);
        reinterpret_cast<uint2*>(g_vh)[i] = r;
        return;
    }
    i -= NV4;
    // region 1: W_v transpose -> fp16
    if (i < EDIM * EDIM) {
        int n = i / KDIM, k = i - n * KDIM;
        g_wv[i] = __float2half(W_v[(size_t)k * EDIM + n]);
        return;
    }
    i -= EDIM * EDIM;
    // region 2: W_off transpose -> bf16 split
    if (i < NOFF * KDIM) {
        int n = i / KDIM, k = i - n * KDIM;
        float x = W_off[(size_t)k * NOFF + n];
        __nv_bfloat16 h = __float2bfloat16(x);
        g_wo_hi[i] = h;
        g_wo_lo[i] = __float2bfloat16(x - __bfloat162float(h));
        return;
    }
    i -= NOFF * KDIM;
    // region 3: W_attn transpose -> fp16
    if (i < NATT * KDIM) {
        int n = i / KDIM, k = i - n * KDIM;
        g_wa[i] = __float2half(W_attn[(size_t)k * NATT + n]);
        return;
    }
    i -= NATT * KDIM;
    // region 4: W_out transpose -> fp16
    if (i < EDIM * EDIM) {
        int n = i / KDIM, k = i - n * KDIM;
        g_wu[i] = __float2half(W_out[(size_t)k * EDIM + n]);
    }
}

// ---------------- tensor-core GEMM (mma.sync) --------------------------------
#define ROWB 80   // padded smem row stride bytes (64B data + 16B pad)

template<bool SPLIT3, typename InT, typename OutT>
__global__ __launch_bounds__(256, 2)
void mma_gemm(const InT* __restrict__ Ahi, const InT* __restrict__ Alo,
              const InT* __restrict__ Bhi, const InT* __restrict__ Blo,
              const float* __restrict__ bias, OutT* __restrict__ C, int N) {
    __shared__ __align__(16) char smA[2][128 * ROWB];
    __shared__ __align__(16) char smB[2][128 * ROWB];

    constexpr int NIT = SPLIT3 ? 3 * NCH : NCH;

    const int tid  = threadIdx.x;
    const int lane = tid & 31;
    const int wid  = tid >> 5;
    const int wm   = (wid >> 1) * 32;
    const int wn   = (wid & 1) * 64;
    const int bm   = blockIdx.y * 128;
    const int bn   = blockIdx.x * 128;

    const uint32_t baseA0 = smem_u32(smA[0]);
    const uint32_t baseA1 = smem_u32(smA[1]);
    const uint32_t baseB0 = smem_u32(smB[0]);
    const uint32_t baseB1 = smem_u32(smB[1]);

    const int lr = tid >> 2;
    const int lc = tid & 3;

    auto issue = [&](int it, int buf) {
        int phase = 0, k0;
        if (SPLIT3) {
            phase = (it >= 2 * NCH) ? 2 : (it >= NCH ? 1 : 0);
            k0 = (it - phase * NCH) * 32;
        } else {
            k0 = it * 32;
        }
        const InT* As = (SPLIT3 && phase == 2) ? Alo : Ahi;
        const InT* Bs = (SPLIT3 && phase == 1) ? Blo : Bhi;
        const uint32_t bA = buf ? baseA1 : baseA0;
        const uint32_t bB = buf ? baseB1 : baseB0;
        #pragma unroll
        for (int i = 0; i < 2; i++) {
            const int r = lr + i * 64;
            const uint32_t dA = bA + r * ROWB + lc * 16;
            const void* gA = As + (size_t)(bm + r) * KDIM + k0 + lc * 8;
            asm volatile("cp.async.cg.shared.global [%0], [%1], 16;"
                         :: "r"(dA), "l"(gA) : "memory");
            const int brow = bn + r;
            const int vsz = (brow < N) ? 16 : 0;
            const uint32_t dB = bB + r * ROWB + lc * 16;
            const void* gB = Bs + (size_t)(brow < N ? brow : 0) * KDIM + k0 + lc * 8;
            asm volatile("cp.async.cg.shared.global [%0], [%1], 16, %2;"
                         :: "r"(dB), "l"(gB), "r"(vsz) : "memory");
        }
        asm volatile("cp.async.commit_group;" ::: "memory");
    };

    float acc[2][8][4] = {};

    issue(0, 0);

    for (int it = 0; it < NIT; it++) {
        const int buf = it & 1;
        if (it + 1 < NIT) {
            issue(it + 1, buf ^ 1);
            asm volatile("cp.async.wait_group 1;" ::: "memory");
        } else {
            asm volatile("cp.async.wait_group 0;" ::: "memory");
        }
        __syncthreads();

        const uint32_t bA = buf ? baseA1 : baseA0;
        const uint32_t bB = buf ? baseB1 : baseB0;

        #pragma unroll
        for (int ks = 0; ks < 2; ks++) {
            uint32_t a[2][4];
            #pragma unroll
            for (int mt = 0; mt < 2; mt++) {
                const uint32_t addr = bA
                    + (uint32_t)(wm + mt * 16 + (lane & 15)) * ROWB
                    + (uint32_t)(ks * 2 + (lane >> 4)) * 16;
                LDSM_X4(a[mt], addr);
            }
            #pragma unroll
            for (int np = 0; np < 4; np++) {
                uint32_t b[4];
                const uint32_t addr = bB
                    + (uint32_t)(wn + np * 16 + ((lane & 16) >> 1) + (lane & 7)) * ROWB
                    + (uint32_t)(ks * 2 + ((lane >> 3) & 1)) * 16;
                LDSM_X4(b, addr);
                #pragma unroll
                for (int mt = 0; mt < 2; mt++) {
                    mma16816<InT>(acc[mt][np * 2],     a[mt], b[0], b[1]);
                    mma16816<InT>(acc[mt][np * 2 + 1], a[mt], b[2], b[3]);
                }
            }
        }
        __syncthreads();
    }

    const int group = lane >> 2, tig = lane & 3;
    #pragma unroll
    for (int mt = 0; mt < 2; mt++) {
        #pragma unroll
        for (int nt = 0; nt < 8; nt++) {
            const int colbase = bn + wn + nt * 8;
            if (colbase >= N) continue;
            const int col = colbase + tig * 2;
            const int m0  = bm + wm + mt * 16 + group;
            const float b0v = bias[col], b1v = bias[col + 1];
            store_out(C, (size_t)m0 * N + col,           acc[mt][nt][0] + b0v);
            store_out(C, (size_t)m0 * N + col + 1,       acc[mt][nt][1] + b1v);
            store_out(C, (size_t)(m0 + 8) * N + col,     acc[mt][nt][2] + b0v);
            store_out(C, (size_t)(m0 + 8) * N + col + 1, acc[mt][nt][3] + b1v);
        }
    }
}

// ---------------- softmax + trilinear deformable sampling --------------------
// One warp = TWO heads of one (b,q); lanes 0-15 head 2p, lanes 16-31 head 2p+1;
// each lane holds 2 channels (half2). Per-point full-outside early-out and
// per-corner weight>0 load predication skip dead gathers entirely.
__global__ __launch_bounds__(256)
void sample_kernel() {
    const int g    = blockIdx.x * 8 + (threadIdx.x >> 5);
    const int lane = threadIdx.x & 31;
    const int pair = g % (HEADS / 2);
    const int bq   = g / (HEADS / 2);
    const int q    = bq % NQ;
    const int b    = bq / NQ;
    const int head = pair * 2 + (lane >> 4);
    const int sl   = lane & 15;

    const float* al = g_attl + (size_t)bq * NATT + head * NPTS;
    float logits[NPTS];
    float mx = -1e30f;
    #pragma unroll
    for (int p = 0; p < NPTS; p++) { logits[p] = al[p]; mx = fmaxf(mx, logits[p]); }
    float ssum = 0.f;
    #pragma unroll
    for (int p = 0; p < NPTS; p++) { logits[p] = __expf(logits[p] - mx); ssum += logits[p]; }
    const float inv = 1.f / ssum;

    const int qx = q % WIDW;
    const int qy = q / WIDW;
    const float rpx = qx + 0.5f;
    const float rpy = qy + 0.5f;

    const float* off = g_offs + (size_t)bq * NOFF + head * (NPTS * 3);
    const __half2* vb = reinterpret_cast<const __half2*>(
        g_vprojH + (size_t)b * NTOK * EDIM + head * 32) + sl;

    float ox = 0.f, oy = 0.f;

    #pragma unroll
    for (int p = 0; p < NPTS; p++) {
        const float ap = logits[p] * inv;
        const float px = rpx + off[p*3 + 0] - 0.5f;
        const float py = rpy + off[p*3 + 1] - 0.5f;
        const float pz = off[p*3 + 2] * (float(DDEP) / 3.0f) - 0.5f;

        // fully-outside early-out: every one of the 8 corners invalid
        if (px < -1.f || px >= (float)WIDW ||
            py < -1.f || py >= (float)HGT  ||
            pz < -1.f || pz >= (float)DDEP) continue;

        const float x0f = floorf(px), y0f = floorf(py), z0f = floorf(pz);
        const float fx = px - x0f, fy = py - y0f, fz = pz - z0f;
        const int ix0 = (int)x0f, iy0 = (int)y0f, iz0 = (int)z0f;

        #pragma unroll
        for (int dz = 0; dz < 2; dz++) {
            const int zi = iz0 + dz;
            if (zi < 0 || zi >= DDEP) continue;
            const float wz = dz ? fz : 1.f - fz;
            #pragma unroll
            for (int dy = 0; dy < 2; dy++) {
                const int yi = iy0 + dy;
                if (yi < 0 || yi >= HGT) continue;
                const float wy = dy ? fy : 1.f - fy;
                #pragma unroll
                for (int dx = 0; dx < 2; dx++) {
                    const int xi = ix0 + dx;
                    if (xi < 0 || xi >= WIDW) continue;
                    const float w = ap * wz * wy * (dx ? fx : 1.f - fx);
                    if (w > 0.f) {
                        const int t = (zi * HGT + yi) * WIDW + xi;
                        const float2 vf = __half22float2(vb[(size_t)t * (EDIM / 2)]);
                        ox += w * vf.x;
                        oy += w * vf.y;
                    }
                }
            }
        }
    }

    reinterpret_cast<__half2*>(g_sampH + (size_t)bq * EDIM + head * 32)[sl] =
        __floats2half2_rn(ox, oy);
}

// ---------------- launch ------------------------------------------------------
extern "C" void kernel_launch(void* const* d_in, const int* in_sizes, int n_in,
                              void* d_out, int out_size) {
    const float* query     = (const float*)d_in[0];
    const float* value     = (const float*)d_in[1];
    const float* query_pos = (const float*)d_in[2];
    const float* W_off     = (const float*)d_in[3];
    const float* b_off     = (const float*)d_in[4];
    const float* W_attn    = (const float*)d_in[5];
    const float* b_attn    = (const float*)d_in[6];
    const float* W_v       = (const float*)d_in[7];
    const float* b_v       = (const float*)d_in[8];
    const float* W_out     = (const float*)d_in[9];
    const float* b_out     = (const float*)d_in[10];
    float* out = (float*)d_out;

    __nv_bfloat16 *qhi, *qlo, *woh, *wol;
    __half *qh, *vh, *vprojH, *sampH, *wv, *wa, *wu;
    float *offs, *attl;
    cudaGetSymbolAddress((void**)&qhi, g_qhi);   cudaGetSymbolAddress((void**)&qlo, g_qlo);
    cudaGetSymbolAddress((void**)&qh,  g_qh);
    cudaGetSymbolAddress((void**)&vh,  g_vh);    cudaGetSymbolAddress((void**)&vprojH, g_vprojH);
    cudaGetSymbolAddress((void**)&sampH, g_sampH);
    cudaGetSymbolAddress((void**)&wv,  g_wv);
    cudaGetSymbolAddress((void**)&woh, g_wo_hi); cudaGetSymbolAddress((void**)&wol, g_wo_lo);
    cudaGetSymbolAddress((void**)&wa,  g_wa);    cudaGetSymbolAddress((void**)&wu,  g_wu);
    cudaGetSymbolAddress((void**)&offs, g_offs);
    cudaGetSymbolAddress((void**)&attl, g_attl);

    // launch 1: q + query_pos -> bf16 split + fp16
    { int n = BSZ*NQ*EDIM;
      addsplit3_kernel<<<(n+255)/256, 256>>>(query, query_pos, qhi, qlo, qh, n); }
    // launch 2: value -> fp16 + all weight conversions
    {
        int total = NV4 + EDIM*EDIM + NOFF*KDIM + NATT*KDIM + EDIM*EDIM;
        megaconv_kernel<<<(total+255)/256, 256>>>(value, W_v, W_off, W_attn, W_out);
    }
    // launch 3: vproj = value @ W_v + b_v   (M=51200, N=576) fp16
    {
        dim3 grid((EDIM + 127) / 128, (BSZ * NTOK) / 128);
        mma_gemm<false, __half, __half><<<grid, 256>>>(vh, vh, wv, wv, b_v, vprojH, EDIM);
    }
    // launch 4: offs = q @ W_off + b_off    (M=10240, N=648) bf16 split3
    {
        dim3 grid((NOFF + 127) / 128, (BSZ * NQ) / 128);
        mma_gemm<true, __nv_bfloat16, float><<<grid, 256>>>(qhi, qlo, woh, wol, b_off, offs, NOFF);
    }
    // launch 5: attl = q @ W_attn + b_attn  (M=10240, N=216) fp16
    {
        dim3 grid((NATT + 127) / 128, (BSZ * NQ) / 128);
        mma_gemm<false, __half, float><<<grid, 256>>>(qh, qh, wa, wa, b_attn, attl, NATT);
    }
    // launch 6 (ncu -s 5 captures this): softmax + trilinear sampling
    {
        int warps = BSZ * NQ * (HEADS / 2);    // 92160
        sample_kernel<<<warps / 8, 256>>>();
    }
    // launch 7: out = samp @ W_out + b_out  (M=10240, N=576) fp16
    {
        dim3 grid((EDIM + 127) / 128, (BSZ * NQ) / 128);
        mma_gemm<false, __half, float><<<grid, 256>>>(sampH, sampH, wu, wu, b_out, out, EDIM);
    }
}

// round 13
// speedup vs baseline: 5.4431x; 1.0494x over previous
#include <cuda_runtime.h>
#include <cuda_bf16.h>
#include <cuda_fp16.h>
#include <cstdint>

// ---------------- problem constants ----------------
#define BSZ   2
#define NQ    5120
#define EDIM  576
#define HEADS 18
#define NPTS  12
#define DDEP  5
#define HGT   64
#define WIDW  80
#define NTOK  (NQ*DDEP)        // 25600
#define NOFF  (HEADS*NPTS*3)   // 648
#define NATT  (HEADS*NPTS)     // 216
#define KDIM  576
#define NCH   18               // K chunks of 32
#define NV4   ((BSZ*NTOK*EDIM)/4)   // float4 count of value

// ---------------- scratch (device globals) -----------------------------------
__device__ __align__(16) __nv_bfloat16 g_qhi [BSZ*NQ*EDIM];
__device__ __align__(16) __nv_bfloat16 g_qlo [BSZ*NQ*EDIM];
__device__ __align__(16) __half        g_qh  [BSZ*NQ*EDIM];
__device__ __align__(16) __half        g_vh  [BSZ*NTOK*EDIM];
__device__ __align__(16) __half        g_vprojH[BSZ*NTOK*EDIM];
__device__ __align__(16) float         g_offs [BSZ*NQ*NOFF];
__device__ __align__(16) float         g_attl [BSZ*NQ*NATT];
__device__ __align__(16) __half        g_sampH[BSZ*NQ*EDIM];
// transposed weights: [N][K] K-major
__device__ __align__(16) __half        g_wv  [EDIM*EDIM];
__device__ __align__(16) __nv_bfloat16 g_wo_hi [NOFF*EDIM];
__device__ __align__(16) __nv_bfloat16 g_wo_lo [NOFF*EDIM];
__device__ __align__(16) __half        g_wa  [NATT*EDIM];
__device__ __align__(16) __half        g_wu  [EDIM*EDIM];

// ---------------- helpers -----------------------------------------------------
__device__ __forceinline__ uint32_t smem_u32(const void* p) {
    uint32_t a;
    asm("{ .reg .u64 t; cvta.to.shared.u64 t, %1; cvt.u32.u64 %0, t; }" : "=r"(a) : "l"(p));
    return a;
}
template<typename T>
__device__ __forceinline__ void mma16816(float* c, const uint32_t* a, uint32_t b0, uint32_t b1);
template<>
__device__ __forceinline__ void mma16816<__nv_bfloat16>(float* c, const uint32_t* a, uint32_t b0, uint32_t b1) {
    asm volatile("mma.sync.aligned.m16n8k16.row.col.f32.bf16.bf16.f32 "
        "{%0,%1,%2,%3}, {%4,%5,%6,%7}, {%8,%9}, {%0,%1,%2,%3};"
        : "+f"(c[0]), "+f"(c[1]), "+f"(c[2]), "+f"(c[3])
        : "r"(a[0]), "r"(a[1]), "r"(a[2]), "r"(a[3]), "r"(b0), "r"(b1));
}
template<>
__device__ __forceinline__ void mma16816<__half>(float* c, const uint32_t* a, uint32_t b0, uint32_t b1) {
    asm volatile("mma.sync.aligned.m16n8k16.row.col.f32.f16.f16.f32 "
        "{%0,%1,%2,%3}, {%4,%5,%6,%7}, {%8,%9}, {%0,%1,%2,%3};"
        : "+f"(c[0]), "+f"(c[1]), "+f"(c[2]), "+f"(c[3])
        : "r"(a[0]), "r"(a[1]), "r"(a[2]), "r"(a[3]), "r"(b0), "r"(b1));
}
#define LDSM_X4(d, addr) \
    asm volatile("ldmatrix.sync.aligned.m8n8.x4.shared.b16 {%0,%1,%2,%3}, [%4];" \
        : "=r"((d)[0]), "=r"((d)[1]), "=r"((d)[2]), "=r"((d)[3]) : "r"(addr))

__device__ __forceinline__ void store_out(float* C, size_t idx, float v) { C[idx] = v; }
__device__ __forceinline__ void store_out(__half* C, size_t idx, float v) { C[idx] = __float2half(v); }

// ---------------- conversion kernels -----------------------------------------
__global__ void addsplit3_kernel(const float* __restrict__ a, const float* __restrict__ b,
                                 __nv_bfloat16* __restrict__ hi, __nv_bfloat16* __restrict__ lo,
                                 __half* __restrict__ h16, int n) {
    int i = blockIdx.x * blockDim.x + threadIdx.x;
    if (i < n) {
        float x = a[i] + b[i];
        __nv_bfloat16 h = __float2bfloat16(x);
        hi[i] = h;
        lo[i] = __float2bfloat16(x - __bfloat162float(h));
        h16[i] = __float2half(x);
    }
}

// One kernel: value -> fp16 (vectorized) + all weight transposes/conversions.
__global__ void megaconv_kernel(const float* __restrict__ value,
                                const float* __restrict__ W_v,
                                const float* __restrict__ W_off,
                                const float* __restrict__ W_attn,
                                const float* __restrict__ W_out) {
    int i = blockIdx.x * blockDim.x + threadIdx.x;
    if (i < NV4) {
        float4 v = reinterpret_cast<const float4*>(value)[i];
        __half2 h0 = __floats2half2_rn(v.x, v.y);
        __half2 h1 = __floats2half2_rn(v.z, v.w);
        uint2 r;
        r.x = *reinterpret_cast<uint32_t*>(&h0);
        r.y = *reinterpret_cast<uint32_t*>(&h1);
        reinterpret_cast<uint2*>(g_vh)[i] = r;
        return;
    }
    i -= NV4;
    if (i < EDIM * EDIM) {
        int n = i / KDIM, k = i - n * KDIM;
        g_wv[i] = __float2half(W_v[(size_t)k * EDIM + n]);
        return;
    }
    i -= EDIM * EDIM;
    if (i < NOFF * KDIM) {
        int n = i / KDIM, k = i - n * KDIM;
        float x = W_off[(size_t)k * NOFF + n];
        __nv_bfloat16 h = __float2bfloat16(x);
        g_wo_hi[i] = h;
        g_wo_lo[i] = __float2bfloat16(x - __bfloat162float(h));
        return;
    }
    i -= NOFF * KDIM;
    if (i < NATT * KDIM) {
        int n = i / KDIM, k = i - n * KDIM;
        g_wa[i] = __float2half(W_attn[(size_t)k * NATT + n]);
        return;
    }
    i -= NATT * KDIM;
    if (i < EDIM * EDIM) {
        int n = i / KDIM, k = i - n * KDIM;
        g_wu[i] = __float2half(W_out[(size_t)k * EDIM + n]);
    }
}

// ---------------- tensor-core GEMM (mma.sync) with zero-block skip -----------
#define ROWB 80   // padded smem row stride bytes (64B data + 16B pad)

template<bool SPLIT3, typename InT, typename OutT>
__global__ __launch_bounds__(256, 2)
void mma_gemm(const InT* __restrict__ Ahi, const InT* __restrict__ Alo,
              const InT* __restrict__ Bhi, const InT* __restrict__ Blo,
              const float* __restrict__ bias, OutT* __restrict__ C, int N) {
    __shared__ __align__(16) char smA[2][128 * ROWB];
    __shared__ __align__(16) char smB[2][128 * ROWB];

    constexpr int NIT = SPLIT3 ? 3 * NCH : NCH;

    const int tid  = threadIdx.x;
    const int lane = tid & 31;
    const int wid  = tid >> 5;
    const int wm   = (wid >> 1) * 32;
    const int wn   = (wid & 1) * 64;
    const int bm   = blockIdx.y * 128;
    const int bn   = blockIdx.x * 128;

    const uint32_t baseA0 = smem_u32(smA[0]);
    const uint32_t baseA1 = smem_u32(smA[1]);
    const uint32_t baseB0 = smem_u32(smB[0]);
    const uint32_t baseB1 = smem_u32(smB[1]);

    const int lr = tid >> 2;
    const int lc = tid & 3;

    auto issue = [&](int it, int buf) {
        int phase = 0, k0;
        if (SPLIT3) {
            phase = (it >= 2 * NCH) ? 2 : (it >= NCH ? 1 : 0);
            k0 = (it - phase * NCH) * 32;
        } else {
            k0 = it * 32;
        }
        const InT* As = (SPLIT3 && phase == 2) ? Alo : Ahi;
        const InT* Bs = (SPLIT3 && phase == 1) ? Blo : Bhi;
        const uint32_t bA = buf ? baseA1 : baseA0;
        const uint32_t bB = buf ? baseB1 : baseB0;
        #pragma unroll
        for (int i = 0; i < 2; i++) {
            const int r = lr + i * 64;
            const uint32_t dA = bA + r * ROWB + lc * 16;
            const void* gA = As + (size_t)(bm + r) * KDIM + k0 + lc * 8;
            asm volatile("cp.async.cg.shared.global [%0], [%1], 16;"
                         :: "r"(dA), "l"(gA) : "memory");
            const int brow = bn + r;
            const int vsz = (brow < N) ? 16 : 0;
            const uint32_t dB = bB + r * ROWB + lc * 16;
            const void* gB = Bs + (size_t)(brow < N ? brow : 0) * KDIM + k0 + lc * 8;
            asm volatile("cp.async.cg.shared.global [%0], [%1], 16, %2;"
                         :: "r"(dB), "l"(gB), "r"(vsz) : "memory");
        }
        asm volatile("cp.async.commit_group;" ::: "memory");
    };

    float acc[2][8][4] = {};

    issue(0, 0);

    for (int it = 0; it < NIT; it++) {
        const int buf = it & 1;
        if (it + 1 < NIT) {
            issue(it + 1, buf ^ 1);
            asm volatile("cp.async.wait_group 1;" ::: "memory");
        } else {
            asm volatile("cp.async.wait_group 0;" ::: "memory");
        }

        // zero-block detection: each thread inspects exactly the B bytes it
        // just cp.async'd (self-visible after wait_group). __syncthreads_or
        // doubles as the cross-thread visibility barrier for the compute.
        int lnz;
        {
            const uint4 v0 = *reinterpret_cast<const uint4*>(smB[buf] + lr * ROWB + lc * 16);
            const uint4 v1 = *reinterpret_cast<const uint4*>(smB[buf] + (lr + 64) * ROWB + lc * 16);
            lnz = (v0.x | v0.y | v0.z | v0.w | v1.x | v1.y | v1.z | v1.w) != 0u;
        }
        const int nz = __syncthreads_or(lnz);

        if (nz) {
            const uint32_t bA = buf ? baseA1 : baseA0;
            const uint32_t bB = buf ? baseB1 : baseB0;

            #pragma unroll
            for (int ks = 0; ks < 2; ks++) {
                uint32_t a[2][4];
                #pragma unroll
                for (int mt = 0; mt < 2; mt++) {
                    const uint32_t addr = bA
                        + (uint32_t)(wm + mt * 16 + (lane & 15)) * ROWB
                        + (uint32_t)(ks * 2 + (lane >> 4)) * 16;
                    LDSM_X4(a[mt], addr);
                }
                #pragma unroll
                for (int np = 0; np < 4; np++) {
                    uint32_t b[4];
                    const uint32_t addr = bB
                        + (uint32_t)(wn + np * 16 + ((lane & 16) >> 1) + (lane & 7)) * ROWB
                        + (uint32_t)(ks * 2 + ((lane >> 3) & 1)) * 16;
                    LDSM_X4(b, addr);
                    #pragma unroll
                    for (int mt = 0; mt < 2; mt++) {
                        mma16816<InT>(acc[mt][np * 2],     a[mt], b[0], b[1]);
                        mma16816<InT>(acc[mt][np * 2 + 1], a[mt], b[2], b[3]);
                    }
                }
            }
        }
        __syncthreads();
    }

    const int group = lane >> 2, tig = lane & 3;
    #pragma unroll
    for (int mt = 0; mt < 2; mt++) {
        #pragma unroll
        for (int nt = 0; nt < 8; nt++) {
            const int colbase = bn + wn + nt * 8;
            if (colbase >= N) continue;
            const int col = colbase + tig * 2;
            const int m0  = bm + wm + mt * 16 + group;
            const float b0v = bias[col], b1v = bias[col + 1];
            store_out(C, (size_t)m0 * N + col,           acc[mt][nt][0] + b0v);
            store_out(C, (size_t)m0 * N + col + 1,       acc[mt][nt][1] + b1v);
            store_out(C, (size_t)(m0 + 8) * N + col,     acc[mt][nt][2] + b0v);
            store_out(C, (size_t)(m0 + 8) * N + col + 1, acc[mt][nt][3] + b1v);
        }
    }
}

// ---------------- softmax + trilinear deformable sampling --------------------
__global__ __launch_bounds__(256)
void sample_kernel() {
    const int g    = blockIdx.x * 8 + (threadIdx.x >> 5);
    const int lane = threadIdx.x & 31;
    const int pair = g % (HEADS / 2);
    const int bq   = g / (HEADS / 2);
    const int q    = bq % NQ;
    const int b    = bq / NQ;
    const int head = pair * 2 + (lane >> 4);
    const int sl   = lane & 15;

    const float* al = g_attl + (size_t)bq * NATT + head * NPTS;
    float logits[NPTS];
    float mx = -1e30f;
    #pragma unroll
    for (int p = 0; p < NPTS; p++) { logits[p] = al[p]; mx = fmaxf(mx, logits[p]); }
    float ssum = 0.f;
    #pragma unroll
    for (int p = 0; p < NPTS; p++) { logits[p] = __expf(logits[p] - mx); ssum += logits[p]; }
    const float inv = 1.f / ssum;

    const int qx = q % WIDW;
    const int qy = q / WIDW;
    const float rpx = qx + 0.5f;
    const float rpy = qy + 0.5f;

    const float* off = g_offs + (size_t)bq * NOFF + head * (NPTS * 3);
    const __half2* vb = reinterpret_cast<const __half2*>(
        g_vprojH + (size_t)b * NTOK * EDIM + head * 32) + sl;

    float ox = 0.f, oy = 0.f;

    #pragma unroll
    for (int p = 0; p < NPTS; p++) {
        const float ap = logits[p] * inv;
        const float px = rpx + off[p*3 + 0] - 0.5f;
        const float py = rpy + off[p*3 + 1] - 0.5f;
        const float pz = off[p*3 + 2] * (float(DDEP) / 3.0f) - 0.5f;

        if (px < -1.f || px >= (float)WIDW ||
            py < -1.f || py >= (float)HGT  ||
            pz < -1.f || pz >= (float)DDEP) continue;

        const float x0f = floorf(px), y0f = floorf(py), z0f = floorf(pz);
        const float fx = px - x0f, fy = py - y0f, fz = pz - z0f;
        const int ix0 = (int)x0f, iy0 = (int)y0f, iz0 = (int)z0f;

        #pragma unroll
        for (int dz = 0; dz < 2; dz++) {
            const int zi = iz0 + dz;
            if (zi < 0 || zi >= DDEP) continue;
            const float wz = dz ? fz : 1.f - fz;
            #pragma unroll
            for (int dy = 0; dy < 2; dy++) {
                const int yi = iy0 + dy;
                if (yi < 0 || yi >= HGT) continue;
                const float wy = dy ? fy : 1.f - fy;
                #pragma unroll
                for (int dx = 0; dx < 2; dx++) {
                    const int xi = ix0 + dx;
                    if (xi < 0 || xi >= WIDW) continue;
                    const float w = ap * wz * wy * (dx ? fx : 1.f - fx);
                    if (w > 0.f) {
                        const int t = (zi * HGT + yi) * WIDW + xi;
                        const float2 vf = __half22float2(vb[(size_t)t * (EDIM / 2)]);
                        ox += w * vf.x;
                        oy += w * vf.y;
                    }
                }
            }
        }
    }

    reinterpret_cast<__half2*>(g_sampH + (size_t)bq * EDIM + head * 32)[sl] =
        __floats2half2_rn(ox, oy);
}

// ---------------- launch ------------------------------------------------------
extern "C" void kernel_launch(void* const* d_in, const int* in_sizes, int n_in,
                              void* d_out, int out_size) {
    const float* query     = (const float*)d_in[0];
    const float* value     = (const float*)d_in[1];
    const float* query_pos = (const float*)d_in[2];
    const float* W_off     = (const float*)d_in[3];
    const float* b_off     = (const float*)d_in[4];
    const float* W_attn    = (const float*)d_in[5];
    const float* b_attn    = (const float*)d_in[6];
    const float* W_v       = (const float*)d_in[7];
    const float* b_v       = (const float*)d_in[8];
    const float* W_out     = (const float*)d_in[9];
    const float* b_out     = (const float*)d_in[10];
    float* out = (float*)d_out;

    __nv_bfloat16 *qhi, *qlo, *woh, *wol;
    __half *qh, *vh, *vprojH, *sampH, *wv, *wa, *wu;
    float *offs, *attl;
    cudaGetSymbolAddress((void**)&qhi, g_qhi);   cudaGetSymbolAddress((void**)&qlo, g_qlo);
    cudaGetSymbolAddress((void**)&qh,  g_qh);
    cudaGetSymbolAddress((void**)&vh,  g_vh);    cudaGetSymbolAddress((void**)&vprojH, g_vprojH);
    cudaGetSymbolAddress((void**)&sampH, g_sampH);
    cudaGetSymbolAddress((void**)&wv,  g_wv);
    cudaGetSymbolAddress((void**)&woh, g_wo_hi); cudaGetSymbolAddress((void**)&wol, g_wo_lo);
    cudaGetSymbolAddress((void**)&wa,  g_wa);    cudaGetSymbolAddress((void**)&wu,  g_wu);
    cudaGetSymbolAddress((void**)&offs, g_offs);
    cudaGetSymbolAddress((void**)&attl, g_attl);

    // launch 1: q + query_pos -> bf16 split + fp16
    { int n = BSZ*NQ*EDIM;
      addsplit3_kernel<<<(n+255)/256, 256>>>(query, query_pos, qhi, qlo, qh, n); }
    // launch 2: value -> fp16 + all weight conversions
    {
        int total = NV4 + EDIM*EDIM + NOFF*KDIM + NATT*KDIM + EDIM*EDIM;
        megaconv_kernel<<<(total+255)/256, 256>>>(value, W_v, W_off, W_attn, W_out);
    }
    // launch 3: vproj = value @ W_v + b_v   (M=51200, N=576) fp16
    {
        dim3 grid((EDIM + 127) / 128, (BSZ * NTOK) / 128);
        mma_gemm<false, __half, __half><<<grid, 256>>>(vh, vh, wv, wv, b_v, vprojH, EDIM);
    }
    // launch 4: offs = q @ W_off + b_off    (M=10240, N=648) bf16 split3
    {
        dim3 grid((NOFF + 127) / 128, (BSZ * NQ) / 128);
        mma_gemm<true, __nv_bfloat16, float><<<grid, 256>>>(qhi, qlo, woh, wol, b_off, offs, NOFF);
    }
    // launch 5: attl = q @ W_attn + b_attn  (M=10240, N=216) fp16
    {
        dim3 grid((NATT + 127) / 128, (BSZ * NQ) / 128);
        mma_gemm<false, __half, float><<<grid, 256>>>(qh, qh, wa, wa, b_attn, attl, NATT);
    }
    // launch 6 (ncu -s 5 captures this): softmax + trilinear sampling
    {
        int warps = BSZ * NQ * (HEADS / 2);    // 92160
        sample_kernel<<<warps / 8, 256>>>();
    }
    // launch 7: out = samp @ W_out + b_out  (M=10240, N=576) fp16
    {
        dim3 grid((EDIM + 127) / 128, (BSZ * NQ) / 128);
        mma_gemm<false, __half, float><<<grid, 256>>>(sampH, sampH, wu, wu, b_out, out, EDIM);
    }
}

// round 15
// speedup vs baseline: 6.2324x; 1.1450x over previous
#include <cuda_runtime.h>
#include <cuda_bf16.h>
#include <cuda_fp16.h>
#include <cstdint>

// ---------------- problem constants ----------------
#define BSZ   2
#define NQ    5120
#define EDIM  576
#define HEADS 18
#define NPTS  12
#define DDEP  5
#define HGT   64
#define WIDW  80
#define NTOK  (NQ*DDEP)        // 25600
#define NOFF  (HEADS*NPTS*3)   // 648
#define NATT  (HEADS*NPTS)     // 216
#define KDIM  576
#define NCH   18               // K chunks of 32
#define NV4   ((BSZ*NTOK*EDIM)/4)   // float4 count of value

// nonzero-flag table layout (ints): per weight matrix, [nblock][kchunk]
#define NZ_WV  0      // 5*18 = 90
#define NZ_WA  90     // 2*18 = 36
#define NZ_WU  126    // 5*18 = 90
#define NZ_WOH 216    // 6*18 = 108
#define NZ_WOL 324    // 6*18 = 108
#define NZ_TOT 432

// ---------------- scratch (device globals) -----------------------------------
__device__ __align__(16) __nv_bfloat16 g_qhi [BSZ*NQ*EDIM];
__device__ __align__(16) __nv_bfloat16 g_qlo [BSZ*NQ*EDIM];
__device__ __align__(16) __half        g_qh  [BSZ*NQ*EDIM];
__device__ __align__(16) __half        g_vh  [BSZ*NTOK*EDIM];
__device__ __align__(16) __half        g_vprojH[BSZ*NTOK*EDIM];
__device__ __align__(16) float         g_offs [BSZ*NQ*NOFF];
__device__ __align__(16) float         g_attl [BSZ*NQ*NATT];
__device__ __align__(16) __half        g_sampH[BSZ*NQ*EDIM];
// transposed weights: [N][K] K-major
__device__ __align__(16) __half        g_wv  [EDIM*EDIM];
__device__ __align__(16) __nv_bfloat16 g_wo_hi [NOFF*EDIM];
__device__ __align__(16) __nv_bfloat16 g_wo_lo [NOFF*EDIM];
__device__ __align__(16) __half        g_wa  [NATT*EDIM];
__device__ __align__(16) __half        g_wu  [EDIM*EDIM];
__device__ int g_nz[NZ_TOT];

// ---------------- helpers -----------------------------------------------------
__device__ __forceinline__ uint32_t smem_u32(const void* p) {
    uint32_t a;
    asm("{ .reg .u64 t; cvta.to.shared.u64 t, %1; cvt.u32.u64 %0, t; }" : "=r"(a) : "l"(p));
    return a;
}
template<typename T>
__device__ __forceinline__ void mma16816(float* c, const uint32_t* a, uint32_t b0, uint32_t b1);
template<>
__device__ __forceinline__ void mma16816<__nv_bfloat16>(float* c, const uint32_t* a, uint32_t b0, uint32_t b1) {
    asm volatile("mma.sync.aligned.m16n8k16.row.col.f32.bf16.bf16.f32 "
        "{%0,%1,%2,%3}, {%4,%5,%6,%7}, {%8,%9}, {%0,%1,%2,%3};"
        : "+f"(c[0]), "+f"(c[1]), "+f"(c[2]), "+f"(c[3])
        : "r"(a[0]), "r"(a[1]), "r"(a[2]), "r"(a[3]), "r"(b0), "r"(b1));
}
template<>
__device__ __forceinline__ void mma16816<__half>(float* c, const uint32_t* a, uint32_t b0, uint32_t b1) {
    asm volatile("mma.sync.aligned.m16n8k16.row.col.f32.f16.f16.f32 "
        "{%0,%1,%2,%3}, {%4,%5,%6,%7}, {%8,%9}, {%0,%1,%2,%3};"
        : "+f"(c[0]), "+f"(c[1]), "+f"(c[2]), "+f"(c[3])
        : "r"(a[0]), "r"(a[1]), "r"(a[2]), "r"(a[3]), "r"(b0), "r"(b1));
}
#define LDSM_X4(d, addr) \
    asm volatile("ldmatrix.sync.aligned.m8n8.x4.shared.b16 {%0,%1,%2,%3}, [%4];" \
        : "=r"((d)[0]), "=r"((d)[1]), "=r"((d)[2]), "=r"((d)[3]) : "r"(addr))

__device__ __forceinline__ void store_out(float* C, size_t idx, float v) { C[idx] = v; }
__device__ __forceinline__ void store_out(__half* C, size_t idx, float v) { C[idx] = __float2half(v); }

// ---------------- conversion kernels -----------------------------------------
// Also zeroes the nonzero-flag table (runs before megaconv, stream-ordered).
__global__ void addsplit3_kernel(const float* __restrict__ a, const float* __restrict__ b,
                                 __nv_bfloat16* __restrict__ hi, __nv_bfloat16* __restrict__ lo,
                                 __half* __restrict__ h16, int n) {
    int i = blockIdx.x * blockDim.x + threadIdx.x;
    if (i < NZ_TOT) g_nz[i] = 0;
    if (i < n) {
        float x = a[i] + b[i];
        __nv_bfloat16 h = __float2bfloat16(x);
        hi[i] = h;
        lo[i] = __float2bfloat16(x - __bfloat162float(h));
        h16[i] = __float2half(x);
    }
}

// value -> fp16 + all weight transposes/conversions + nonzero flags.
__global__ void megaconv_kernel(const float* __restrict__ value,
                                const float* __restrict__ W_v,
                                const float* __restrict__ W_off,
                                const float* __restrict__ W_attn,
                                const float* __restrict__ W_out) {
    int i = blockIdx.x * blockDim.x + threadIdx.x;
    if (i < NV4) {
        float4 v = reinterpret_cast<const float4*>(value)[i];
        __half2 h0 = __floats2half2_rn(v.x, v.y);
        __half2 h1 = __floats2half2_rn(v.z, v.w);
        uint2 r;
        r.x = *reinterpret_cast<uint32_t*>(&h0);
        r.y = *reinterpret_cast<uint32_t*>(&h1);
        reinterpret_cast<uint2*>(g_vh)[i] = r;
        return;
    }
    i -= NV4;
    if (i < EDIM * EDIM) {
        int n = i / KDIM, k = i - n * KDIM;
        __half h = __float2half(W_v[(size_t)k * EDIM + n]);
        g_wv[i] = h;
        if (__half_as_ushort(h) != 0)
            g_nz[NZ_WV + (n >> 7) * NCH + (k >> 5)] = 1;
        return;
    }
    i -= EDIM * EDIM;
    if (i < NOFF * KDIM) {
        int n = i / KDIM, k = i - n * KDIM;
        float x = W_off[(size_t)k * NOFF + n];
        __nv_bfloat16 h = __float2bfloat16(x);
        __nv_bfloat16 l = __float2bfloat16(x - __bfloat162float(h));
        g_wo_hi[i] = h;
        g_wo_lo[i] = l;
        const int fidx = (n >> 7) * NCH + (k >> 5);
        if (__bfloat16_as_ushort(h) != 0) g_nz[NZ_WOH + fidx] = 1;
        if (__bfloat16_as_ushort(l) != 0) g_nz[NZ_WOL + fidx] = 1;
        return;
    }
    i -= NOFF * KDIM;
    if (i < NATT * KDIM) {
        int n = i / KDIM, k = i - n * KDIM;
        __half h = __float2half(W_attn[(size_t)k * NATT + n]);
        g_wa[i] = h;
        if (__half_as_ushort(h) != 0)
            g_nz[NZ_WA + (n >> 7) * NCH + (k >> 5)] = 1;
        return;
    }
    i -= NATT * KDIM;
    if (i < EDIM * EDIM) {
        int n = i / KDIM, k = i - n * KDIM;
        __half h = __float2half(W_out[(size_t)k * EDIM + n]);
        g_wu[i] = h;
        if (__half_as_ushort(h) != 0)
            g_nz[NZ_WU + (n >> 7) * NCH + (k >> 5)] = 1;
    }
}

// ---------------- tensor-core GEMM (mma.sync) with flag-based chunk skip -----
#define ROWB 80   // padded smem row stride bytes (64B data + 16B pad)

template<bool SPLIT3, typename InT, typename OutT>
__global__ __launch_bounds__(256, 2)
void mma_gemm(const InT* __restrict__ Ahi, const InT* __restrict__ Alo,
              const InT* __restrict__ Bhi, const InT* __restrict__ Blo,
              const float* __restrict__ bias, OutT* __restrict__ C, int N,
              const int* __restrict__ nzHi, const int* __restrict__ nzLo) {
    __shared__ __align__(16) char smA[2][128 * ROWB];
    __shared__ __align__(16) char smB[2][128 * ROWB];

    constexpr int NIT = SPLIT3 ? 3 * NCH : NCH;
    __shared__ int sflags[NIT];

    const int tid  = threadIdx.x;
    const int lane = tid & 31;
    const int wid  = tid >> 5;
    const int wm   = (wid >> 1) * 32;
    const int wn   = (wid & 1) * 64;
    const int bm   = blockIdx.y * 128;
    const int bn   = blockIdx.x * 128;

    // preload this n-block's chunk flags
    if (tid < NIT) {
        int phase = SPLIT3 ? tid / NCH : 0;
        int kc    = SPLIT3 ? tid - phase * NCH : tid;
        const int* nz = (SPLIT3 && phase == 1) ? nzLo : nzHi;
        sflags[tid] = nz[blockIdx.x * NCH + kc];
    }
    __syncthreads();

    const uint32_t baseA0 = smem_u32(smA[0]);
    const uint32_t baseA1 = smem_u32(smA[1]);
    const uint32_t baseB0 = smem_u32(smB[0]);
    const uint32_t baseB1 = smem_u32(smB[1]);

    const int lr = tid >> 2;
    const int lc = tid & 3;

    auto issue = [&](int it, int buf) {
        if (sflags[it]) {
            int phase = 0, k0;
            if (SPLIT3) {
                phase = (it >= 2 * NCH) ? 2 : (it >= NCH ? 1 : 0);
                k0 = (it - phase * NCH) * 32;
            } else {
                k0 = it * 32;
            }
            const InT* As = (SPLIT3 && phase == 2) ? Alo : Ahi;
            const InT* Bs = (SPLIT3 && phase == 1) ? Blo : Bhi;
            const uint32_t bA = buf ? baseA1 : baseA0;
            const uint32_t bB = buf ? baseB1 : baseB0;
            #pragma unroll
            for (int i = 0; i < 2; i++) {
                const int r = lr + i * 64;
                const uint32_t dA = bA + r * ROWB + lc * 16;
                const void* gA = As + (size_t)(bm + r) * KDIM + k0 + lc * 8;
                asm volatile("cp.async.cg.shared.global [%0], [%1], 16;"
                             :: "r"(dA), "l"(gA) : "memory");
                const int brow = bn + r;
                const int vsz = (brow < N) ? 16 : 0;
                const uint32_t dB = bB + r * ROWB + lc * 16;
                const void* gB = Bs + (size_t)(brow < N ? brow : 0) * KDIM + k0 + lc * 8;
                asm volatile("cp.async.cg.shared.global [%0], [%1], 16, %2;"
                             :: "r"(dB), "l"(gB), "r"(vsz) : "memory");
            }
        }
        // always commit (possibly empty) so wait_group counts stay aligned
        asm volatile("cp.async.commit_group;" ::: "memory");
    };

    float acc[2][8][4] = {};

    issue(0, 0);

    for (int it = 0; it < NIT; it++) {
        const int buf = it & 1;
        if (it + 1 < NIT) {
            issue(it + 1, buf ^ 1);
            asm volatile("cp.async.wait_group 1;" ::: "memory");
        } else {
            asm volatile("cp.async.wait_group 0;" ::: "memory");
        }
        __syncthreads();

        if (sflags[it]) {
            const uint32_t bA = buf ? baseA1 : baseA0;
            const uint32_t bB = buf ? baseB1 : baseB0;

            #pragma unroll
            for (int ks = 0; ks < 2; ks++) {
                uint32_t a[2][4];
                #pragma unroll
                for (int mt = 0; mt < 2; mt++) {
                    const uint32_t addr = bA
                        + (uint32_t)(wm + mt * 16 + (lane & 15)) * ROWB
                        + (uint32_t)(ks * 2 + (lane >> 4)) * 16;
                    LDSM_X4(a[mt], addr);
                }
                #pragma unroll
                for (int np = 0; np < 4; np++) {
                    uint32_t b[4];
                    const uint32_t addr = bB
                        + (uint32_t)(wn + np * 16 + ((lane & 16) >> 1) + (lane & 7)) * ROWB
                        + (uint32_t)(ks * 2 + ((lane >> 3) & 1)) * 16;
                    LDSM_X4(b, addr);
                    #pragma unroll
                    for (int mt = 0; mt < 2; mt++) {
                        mma16816<InT>(acc[mt][np * 2],     a[mt], b[0], b[1]);
                        mma16816<InT>(acc[mt][np * 2 + 1], a[mt], b[2], b[3]);
                    }
                }
            }
        }
        __syncthreads();
    }

    const int group = lane >> 2, tig = lane & 3;
    #pragma unroll
    for (int mt = 0; mt < 2; mt++) {
        #pragma unroll
        for (int nt = 0; nt < 8; nt++) {
            const int colbase = bn + wn + nt * 8;
            if (colbase >= N) continue;
            const int col = colbase + tig * 2;
            const int m0  = bm + wm + mt * 16 + group;
            const float b0v = bias[col], b1v = bias[col + 1];
            store_out(C, (size_t)m0 * N + col,           acc[mt][nt][0] + b0v);
            store_out(C, (size_t)m0 * N + col + 1,       acc[mt][nt][1] + b1v);
            store_out(C, (size_t)(m0 + 8) * N + col,     acc[mt][nt][2] + b0v);
            store_out(C, (size_t)(m0 + 8) * N + col + 1, acc[mt][nt][3] + b1v);
        }
    }
}

// ---------------- softmax + trilinear deformable sampling --------------------
__global__ __launch_bounds__(256)
void sample_kernel() {
    const int g    = blockIdx.x * 8 + (threadIdx.x >> 5);
    const int lane = threadIdx.x & 31;
    const int pair = g % (HEADS / 2);
    const int bq   = g / (HEADS / 2);
    const int q    = bq % NQ;
    const int b    = bq / NQ;
    const int head = pair * 2 + (lane >> 4);
    const int sl   = lane & 15;

    const float* al = g_attl + (size_t)bq * NATT + head * NPTS;
    float logits[NPTS];
    float mx = -1e30f;
    #pragma unroll
    for (int p = 0; p < NPTS; p++) { logits[p] = al[p]; mx = fmaxf(mx, logits[p]); }
    float ssum = 0.f;
    #pragma unroll
    for (int p = 0; p < NPTS; p++) { logits[p] = __expf(logits[p] - mx); ssum += logits[p]; }
    const float inv = 1.f / ssum;

    const int qx = q % WIDW;
    const int qy = q / WIDW;
    const float rpx = qx + 0.5f;
    const float rpy = qy + 0.5f;

    const float* off = g_offs + (size_t)bq * NOFF + head * (NPTS * 3);
    const __half2* vb = reinterpret_cast<const __half2*>(
        g_vprojH + (size_t)b * NTOK * EDIM + head * 32) + sl;

    float ox = 0.f, oy = 0.f;

    #pragma unroll
    for (int p = 0; p < NPTS; p++) {
        const float ap = logits[p] * inv;
        const float px = rpx + off[p*3 + 0] - 0.5f;
        const float py = rpy + off[p*3 + 1] - 0.5f;
        const float pz = off[p*3 + 2] * (float(DDEP) / 3.0f) - 0.5f;

        if (px < -1.f || px >= (float)WIDW ||
            py < -1.f || py >= (float)HGT  ||
            pz < -1.f || pz >= (float)DDEP) continue;

        const float x0f = floorf(px), y0f = floorf(py), z0f = floorf(pz);
        const float fx = px - x0f, fy = py - y0f, fz = pz - z0f;
        const int ix0 = (int)x0f, iy0 = (int)y0f, iz0 = (int)z0f;

        #pragma unroll
        for (int dz = 0; dz < 2; dz++) {
            const int zi = iz0 + dz;
            if (zi < 0 || zi >= DDEP) continue;
            const float wz = dz ? fz : 1.f - fz;
            #pragma unroll
            for (int dy = 0; dy < 2; dy++) {
                const int yi = iy0 + dy;
                if (yi < 0 || yi >= HGT) continue;
                const float wy = dy ? fy : 1.f - fy;
                #pragma unroll
                for (int dx = 0; dx < 2; dx++) {
                    const int xi = ix0 + dx;
                    if (xi < 0 || xi >= WIDW) continue;
                    const float w = ap * wz * wy * (dx ? fx : 1.f - fx);
                    if (w > 0.f) {
                        const int t = (zi * HGT + yi) * WIDW + xi;
                        const float2 vf = __half22float2(vb[(size_t)t * (EDIM / 2)]);
                        ox += w * vf.x;
                        oy += w * vf.y;
                    }
                }
            }
        }
    }

    reinterpret_cast<__half2*>(g_sampH + (size_t)bq * EDIM + head * 32)[sl] =
        __floats2half2_rn(ox, oy);
}

// ---------------- launch ------------------------------------------------------
extern "C" void kernel_launch(void* const* d_in, const int* in_sizes, int n_in,
                              void* d_out, int out_size) {
    const float* query     = (const float*)d_in[0];
    const float* value     = (const float*)d_in[1];
    const float* query_pos = (const float*)d_in[2];
    const float* W_off     = (const float*)d_in[3];
    const float* b_off     = (const float*)d_in[4];
    const float* W_attn    = (const float*)d_in[5];
    const float* b_attn    = (const float*)d_in[6];
    const float* W_v       = (const float*)d_in[7];
    const float* b_v       = (const float*)d_in[8];
    const float* W_out     = (const float*)d_in[9];
    const float* b_out     = (const float*)d_in[10];
    float* out = (float*)d_out;

    __nv_bfloat16 *qhi, *qlo, *woh, *wol;
    __half *qh, *vh, *vprojH, *sampH, *wv, *wa, *wu;
    float *offs, *attl;
    int *nz;
    cudaGetSymbolAddress((void**)&qhi, g_qhi);   cudaGetSymbolAddress((void**)&qlo, g_qlo);
    cudaGetSymbolAddress((void**)&qh,  g_qh);
    cudaGetSymbolAddress((void**)&vh,  g_vh);    cudaGetSymbolAddress((void**)&vprojH, g_vprojH);
    cudaGetSymbolAddress((void**)&sampH, g_sampH);
    cudaGetSymbolAddress((void**)&wv,  g_wv);
    cudaGetSymbolAddress((void**)&woh, g_wo_hi); cudaGetSymbolAddress((void**)&wol, g_wo_lo);
    cudaGetSymbolAddress((void**)&wa,  g_wa);    cudaGetSymbolAddress((void**)&wu,  g_wu);
    cudaGetSymbolAddress((void**)&offs, g_offs);
    cudaGetSymbolAddress((void**)&attl, g_attl);
    cudaGetSymbolAddress((void**)&nz,   g_nz);

    // launch 1: q + query_pos -> bf16 split + fp16 (also zeroes flag table)
    { int n = BSZ*NQ*EDIM;
      addsplit3_kernel<<<(n+255)/256, 256>>>(query, query_pos, qhi, qlo, qh, n); }
    // launch 2: value -> fp16 + weight conversions + nonzero flags
    {
        int total = NV4 + EDIM*EDIM + NOFF*KDIM + NATT*KDIM + EDIM*EDIM;
        megaconv_kernel<<<(total+255)/256, 256>>>(value, W_v, W_off, W_attn, W_out);
    }
    // launch 3: vproj = value @ W_v + b_v   (M=51200, N=576) fp16
    {
        dim3 grid((EDIM + 127) / 128, (BSZ * NTOK) / 128);
        mma_gemm<false, __half, __half><<<grid, 256>>>(vh, vh, wv, wv, b_v, vprojH, EDIM,
                                                       nz + NZ_WV, nz + NZ_WV);
    }
    // launch 4: offs = q @ W_off + b_off    (M=10240, N=648) bf16 split3
    {
        dim3 grid((NOFF + 127) / 128, (BSZ * NQ) / 128);
        mma_gemm<true, __nv_bfloat16, float><<<grid, 256>>>(qhi, qlo, woh, wol, b_off, offs, NOFF,
                                                            nz + NZ_WOH, nz + NZ_WOL);
    }
    // launch 5: attl = q @ W_attn + b_attn  (M=10240, N=216) fp16
    {
        dim3 grid((NATT + 127) / 128, (BSZ * NQ) / 128);
        mma_gemm<false, __half, float><<<grid, 256>>>(qh, qh, wa, wa, b_attn, attl, NATT,
                                                      nz + NZ_WA, nz + NZ_WA);
    }
    // launch 6: softmax + trilinear sampling
    {
        int warps = BSZ * NQ * (HEADS / 2);    // 92160
        sample_kernel<<<warps / 8, 256>>>();
    }
    // launch 7: out = samp @ W_out + b_out  (M=10240, N=576) fp16
    {
        dim3 grid((EDIM + 127) / 128, (BSZ * NQ) / 128);
        mma_gemm<false, __half, float><<<grid, 256>>>(sampH, sampH, wu, wu, b_out, out, EDIM,
                                                      nz + NZ_WU, nz + NZ_WU);
    }
}